// round 8
// baseline (speedup 1.0000x reference)
#include <cuda_runtime.h>
#include <math.h>

// Problem shapes (fixed)
#define B_SZ 1024
#define N_SZ 100000
#define D_SZ 512
#define D4   128               // float4 per row
#define RPW  5                 // rows per warp
#define NWARP 12
#define THREADS (NWARP*32)     // 384
#define BM   (NWARP*RPW)       // 60 rows per CTA
#define BN   32                // keys per tile (1 per lane)
#define NSPLIT 8
#define SPL  (N_SZ/NSPLIT)     // 12500 (exact)
#define NRB  18                // ceil(1024/60)

#define SMEM_BYTES ((BM*D4 + D4*BN)*16)   // 122880 + 65536 = 188416

// Scratch
__device__ float g_ml[B_SZ * NSPLIT * 2];
__device__ float g_acc[(size_t)B_SZ * NSPLIT * D_SZ];
__device__ int   g_cnt[NRB];   // zero-init; last CTA resets after use

typedef unsigned long long u64;
__device__ __forceinline__ u64 pack2(float a, float b) {
    u64 r; asm("mov.b64 %0,{%1,%2};" : "=l"(r) : "f"(a), "f"(b)); return r;
}
__device__ __forceinline__ void unpack2(u64 v, float& a, float& b) {
    asm("mov.b64 {%0,%1},%2;" : "=f"(a), "=f"(b) : "l"(v));
}
__device__ __forceinline__ void ffma2(u64& d, u64 a, u64 b) {
    asm("fma.rn.f32x2 %0,%1,%2,%0;" : "+l"(d) : "l"(a), "l"(b));
}
__device__ __forceinline__ void fmul2(u64& d, u64 a) {
    asm("mul.rn.f32x2 %0,%0,%1;" : "+l"(d) : "l"(a));
}
__device__ __forceinline__ void cp16(unsigned dst, const void* src) {
    asm volatile("cp.async.cg.shared.global [%0], [%1], 16;" :: "r"(dst), "l"(src));
}

// ---------------------------------------------------------------------------
// Fused flash kernel, 12 warps/CTA, 5 rows/warp, 32-key tiles.
// logit'[b][n] = (a/b^2)*<x_b,y_n> - (a^2/(2b^2))*||y_n||^2
// v = (-1/b) x + (1 + a/b) * softmax-weighted dataset
// ---------------------------------------------------------------------------
__global__ __launch_bounds__(THREADS, 1) void flash_kernel(
    const float* __restrict__ x, const float* __restrict__ t,
    const float* __restrict__ y, float* __restrict__ out)
{
    extern __shared__ char smem_raw[];
    ulonglong2* sx = (ulonglong2*)smem_raw;        // BM*D4 float4
    ulonglong2* sy = sx + BM * D4;                 // D4*BN float4, swizzled
    __shared__ int s_last;

    const int tid  = threadIdx.x;
    const int lane = tid & 31;
    const int warp = tid >> 5;
    const int rb      = blockIdx.x;
    const int r0      = rb * BM;
    const int split   = blockIdx.y;
    const int n_begin = split * SPL;
    const int n_end   = n_begin + SPL;             // exact splits

    const unsigned sx_u = (unsigned)__cvta_generic_to_shared(sx);
    const unsigned sy_u = (unsigned)__cvta_generic_to_shared(sy);

    // query tile -> smem (row-clamped for the ragged last row block)
    const float4* x4 = (const float4*)x;
    for (int i = tid; i < BM * D4; i += THREADS) {
        int rc = min(r0 + (i >> 7), B_SZ - 1);
        cp16(sx_u + i * 16, &x4[(size_t)rc * D4 + (i & 127)]);
    }

    // per-row coefficients
    float al[RPW], be[RPW];
    #pragma unroll
    for (int r = 0; r < RPW; r++) {
        int row = min(r0 + warp * RPW + r, B_SZ - 1);
        float tv = t[row];
        float a = tv, b = 1.f - tv;
        al[r] = a / (b * b);
        be[r] = a * a / (2.f * b * b);
    }

    float mrun[RPW], lrun[RPW];
    u64 acc[RPW][8];
    #pragma unroll
    for (int r = 0; r < RPW; r++) {
        mrun[r] = -INFINITY; lrun[r] = 0.f;
        #pragma unroll
        for (int i = 0; i < 8; i++) acc[r][i] = 0ull;
    }

    const float4* y4g = (const float4*)y;

    for (int n0 = n_begin; n0 < n_end; n0 += BN) {
        __syncthreads();   // previous tile's readers done with sy
        // key tile -> smem, swizzled: float4 (n,j) at sy[j*BN + (n ^ (j&31))]
        for (int i = tid; i < BN * D4; i += THREADS) {
            int n = i >> 7, j = i & 127;
            int nc = min(n0 + n, N_SZ - 1);   // clamp (masked later)
            cp16(sy_u + (j * BN + (n ^ (j & 31))) * 16,
                 &y4g[(size_t)nc * D4 + j]);
        }
        asm volatile("cp.async.commit_group;");
        asm volatile("cp.async.wait_group 0;");
        __syncthreads();

        // ---- QK (+ key norms); lane owns key n0+lane ----
        u64 s[RPW];
        #pragma unroll
        for (int r = 0; r < RPW; r++) s[r] = 0ull;
        u64 ny = 0ull;

        #pragma unroll 2
        for (int j = 0; j < D4; j++) {
            int c = j & 31;
            ulonglong2 yv = sy[j * BN + (lane ^ c)];
            ffma2(ny, yv.x, yv.x); ffma2(ny, yv.y, yv.y);
            #pragma unroll
            for (int r = 0; r < RPW; r++) {
                ulonglong2 xv = sx[(warp * RPW + r) * D4 + j];  // broadcast
                ffma2(s[r], xv.x, yv.x); ffma2(s[r], xv.y, yv.y);
            }
        }

        bool vmask = (n0 + lane) < n_end;
        float t0, t1;
        unpack2(ny, t0, t1); float dn = t0 + t1;

        // ---- online softmax (RPW rows), p in registers ----
        float p0[RPW];
        #pragma unroll
        for (int r = 0; r < RPW; r++) {
            float slo, shi;
            unpack2(s[r], slo, shi);
            float lg = vmask ? fmaf(al[r], slo + shi, -be[r] * dn) : -INFINITY;

            float mt = lg;
            #pragma unroll
            for (int off = 16; off > 0; off >>= 1)
                mt = fmaxf(mt, __shfl_xor_sync(0xffffffffu, mt, off));
            if (mt > mrun[r]) {      // rescale only when max moves (warp-uniform)
                float sc = __expf(mrun[r] - mt);   // first tile: exp(-inf)=0
                lrun[r] *= sc;
                u64 scp = pack2(sc, sc);
                #pragma unroll
                for (int i = 0; i < 8; i++) fmul2(acc[r][i], scp);
                mrun[r] = mt;
            }
            p0[r] = __expf(lg - mrun[r]);
            float ps = p0[r];
            #pragma unroll
            for (int off = 16; off > 0; off >>= 1)
                ps += __shfl_xor_sync(0xffffffffu, ps, off);
            lrun[r] += ps;
        }

        // ---- PV: p broadcast via shfl (lane nn owns key n0+nn) ----
        #pragma unroll 2
        for (int nn = 0; nn < BN; nn++) {
            u64 pp[RPW];
            #pragma unroll
            for (int r = 0; r < RPW; r++) {
                float pv = __shfl_sync(0xffffffffu, p0[r], nn);
                pp[r] = pack2(pv, pv);
            }
            #pragma unroll
            for (int k = 0; k < 4; k++) {
                int j = lane + 32 * k;
                ulonglong2 yv = sy[j * BN + (nn ^ (j & 31))];
                #pragma unroll
                for (int r = 0; r < RPW; r++) {
                    ffma2(acc[r][2*k],   pp[r], yv.x);
                    ffma2(acc[r][2*k+1], pp[r], yv.y);
                }
            }
        }
    }

    // ---- write per-(row,split) partials (skip rows >= B) ----
    {
        ulonglong2* gacc2 = (ulonglong2*)g_acc;
        #pragma unroll
        for (int r = 0; r < RPW; r++) {
            int row = r0 + warp * RPW + r;
            if (row < B_SZ) {
                size_t base = ((size_t)row * NSPLIT + split) * D4;
                #pragma unroll
                for (int k = 0; k < 4; k++)
                    gacc2[base + lane + 32 * k] =
                        make_ulonglong2(acc[r][2*k], acc[r][2*k+1]);
                if (lane == 0) {
                    g_ml[(row * NSPLIT + split) * 2 + 0] = mrun[r];
                    g_ml[(row * NSPLIT + split) * 2 + 1] = lrun[r];
                }
            }
        }
    }

    // ---- last-CTA combine epilogue ----
    __threadfence();
    __syncthreads();
    if (tid == 0) {
        int old = atomicAdd(&g_cnt[rb], 1);
        s_last = (old == NSPLIT - 1) ? 1 : 0;
    }
    __syncthreads();
    if (!s_last) return;
    __threadfence();

    // 384 threads: 8 threads/row, 48 rows/pass, 2 passes cover BM=60
    #pragma unroll
    for (int pass = 0; pass < 2; pass++) {
        int rl = pass * 48 + (tid >> 3);
        int row = r0 + rl;
        if (rl < BM && row < B_SZ) {
            int jc = tid & 7;
            float ms[NSPLIT], ls[NSPLIT];
            float M = -INFINITY;
            #pragma unroll
            for (int s = 0; s < NSPLIT; s++) {
                float2 ml = __ldcg((const float2*)&g_ml[(row * NSPLIT + s) * 2]);
                ms[s] = ml.x; ls[s] = ml.y;
                M = fmaxf(M, ms[s]);
            }
            float w[NSPLIT], L = 0.f;
            #pragma unroll
            for (int s = 0; s < NSPLIT; s++) {
                w[s] = __expf(ms[s] - M);
                L = fmaf(w[s], ls[s], L);
            }
            float a = t[row], b = 1.f - a;
            float c1 = -1.f / b;
            float c2 = (1.f + a / b) / L;

            const float4* gacc4 = (const float4*)g_acc;
            #pragma unroll 4
            for (int q = 0; q < 16; q++) {
                int j = jc + 8 * q;
                float4 ws = make_float4(0.f, 0.f, 0.f, 0.f);
                #pragma unroll
                for (int s = 0; s < NSPLIT; s++) {
                    float4 v = __ldcg(&gacc4[((size_t)row * NSPLIT + s) * D4 + j]);
                    ws.x = fmaf(w[s], v.x, ws.x); ws.y = fmaf(w[s], v.y, ws.y);
                    ws.z = fmaf(w[s], v.z, ws.z); ws.w = fmaf(w[s], v.w, ws.w);
                }
                float4 xv = x4[(size_t)row * D4 + j];
                float4 o;
                o.x = fmaf(c1, xv.x, c2 * ws.x);
                o.y = fmaf(c1, xv.y, c2 * ws.y);
                o.z = fmaf(c1, xv.z, c2 * ws.z);
                o.w = fmaf(c1, xv.w, c2 * ws.w);
                ((float4*)out)[(size_t)row * D4 + j] = o;
            }
        }
    }
    __syncthreads();
    if (tid == 0) g_cnt[rb] = 0;   // reset for next graph replay
}

// ---------------------------------------------------------------------------
extern "C" void kernel_launch(void* const* d_in, const int* in_sizes, int n_in,
                              void* d_out, int out_size)
{
    const float* x = (const float*)d_in[0];   // x_t (1024,512)
    const float* t = (const float*)d_in[1];   // t (1024,)
    const float* y = (const float*)d_in[2];   // dataset (100000,512)
    float* out = (float*)d_out;

    cudaFuncSetAttribute(flash_kernel,
                         cudaFuncAttributeMaxDynamicSharedMemorySize, SMEM_BYTES);
    flash_kernel<<<dim3(NRB, NSPLIT), THREADS, SMEM_BYTES>>>(x, t, y, out);
}

// round 9
// speedup vs baseline: 1.0018x; 1.0018x over previous
#include <cuda_runtime.h>
#include <math.h>

// Problem shapes (fixed)
#define B_SZ 1024
#define N_SZ 100000
#define D_SZ 512
#define D4   128               // float4 per row
#define RPW  5                 // rows per warp
#define NWARP 12
#define THREADS (NWARP*32)     // 384
#define BM   (NWARP*RPW)       // 60 rows per CTA
#define BN   32                // keys per tile (1 per lane)
#define NSPLIT 8
#define SPL  (N_SZ/NSPLIT)     // 12500 (exact)
#define NRB  18                // ceil(1024/60)

#define SMEM_BYTES ((BM*D4 + D4*BN)*16)   // 122880 + 65536 = 188416

// Scratch
__device__ float g_ml[B_SZ * NSPLIT * 2];
__device__ float g_acc[(size_t)B_SZ * NSPLIT * D_SZ];
__device__ int   g_cnt[NRB];   // zero-init; last CTA resets after use

typedef unsigned long long u64;
__device__ __forceinline__ u64 pack2(float a, float b) {
    u64 r; asm("mov.b64 %0,{%1,%2};" : "=l"(r) : "f"(a), "f"(b)); return r;
}
__device__ __forceinline__ void unpack2(u64 v, float& a, float& b) {
    asm("mov.b64 {%0,%1},%2;" : "=f"(a), "=f"(b) : "l"(v));
}
__device__ __forceinline__ void ffma2(u64& d, u64 a, u64 b) {
    asm("fma.rn.f32x2 %0,%1,%2,%0;" : "+l"(d) : "l"(a), "l"(b));
}
__device__ __forceinline__ void fmul2(u64& d, u64 a) {
    asm("mul.rn.f32x2 %0,%0,%1;" : "+l"(d) : "l"(a));
}
__device__ __forceinline__ void cp16(unsigned dst, const void* src) {
    asm volatile("cp.async.cg.shared.global [%0], [%1], 16;" :: "r"(dst), "l"(src));
}

// ---------------------------------------------------------------------------
// Fused flash kernel, 12 warps/CTA, 5 rows/warp, 32-key tiles.
// logit'[b][n] = (a/b^2)*<x_b,y_n> - (a^2/(2b^2))*||y_n||^2
// v = (-1/b) x + (1 + a/b) * softmax-weighted dataset
// ---------------------------------------------------------------------------
__global__ __launch_bounds__(THREADS, 1) void flash_kernel(
    const float* __restrict__ x, const float* __restrict__ t,
    const float* __restrict__ y, float* __restrict__ out)
{
    extern __shared__ char smem_raw[];
    ulonglong2* sx = (ulonglong2*)smem_raw;        // BM*D4 float4
    ulonglong2* sy = sx + BM * D4;                 // D4*BN float4, swizzled
    __shared__ int s_last;

    const int tid  = threadIdx.x;
    const int lane = tid & 31;
    const int warp = tid >> 5;
    const int rb      = blockIdx.x;
    const int r0      = rb * BM;
    const int split   = blockIdx.y;
    const int n_begin = split * SPL;
    const int n_end   = n_begin + SPL;             // exact splits

    const unsigned sx_u = (unsigned)__cvta_generic_to_shared(sx);
    const unsigned sy_u = (unsigned)__cvta_generic_to_shared(sy);

    // query tile -> smem (row-clamped for the ragged last row block)
    const float4* x4 = (const float4*)x;
    for (int i = tid; i < BM * D4; i += THREADS) {
        int rc = min(r0 + (i >> 7), B_SZ - 1);
        cp16(sx_u + i * 16, &x4[(size_t)rc * D4 + (i & 127)]);
    }

    // per-row coefficients
    float al[RPW], be[RPW];
    #pragma unroll
    for (int r = 0; r < RPW; r++) {
        int row = min(r0 + warp * RPW + r, B_SZ - 1);
        float tv = t[row];
        float a = tv, b = 1.f - tv;
        al[r] = a / (b * b);
        be[r] = a * a / (2.f * b * b);
    }

    float mrun[RPW], lrun[RPW];
    u64 acc[RPW][8];
    #pragma unroll
    for (int r = 0; r < RPW; r++) {
        mrun[r] = -INFINITY; lrun[r] = 0.f;
        #pragma unroll
        for (int i = 0; i < 8; i++) acc[r][i] = 0ull;
    }

    const float4* y4g = (const float4*)y;

    for (int n0 = n_begin; n0 < n_end; n0 += BN) {
        __syncthreads();   // previous tile's readers done with sy
        // key tile -> smem, swizzled: float4 (n,j) at sy[j*BN + (n ^ (j&31))]
        for (int i = tid; i < BN * D4; i += THREADS) {
            int n = i >> 7, j = i & 127;
            int nc = min(n0 + n, N_SZ - 1);   // clamp (masked later)
            cp16(sy_u + (j * BN + (n ^ (j & 31))) * 16,
                 &y4g[(size_t)nc * D4 + j]);
        }
        asm volatile("cp.async.commit_group;");
        asm volatile("cp.async.wait_group 0;");
        __syncthreads();

        // ---- QK (+ key norms); lane owns key n0+lane ----
        u64 s[RPW];
        #pragma unroll
        for (int r = 0; r < RPW; r++) s[r] = 0ull;
        u64 ny = 0ull;

        #pragma unroll 2
        for (int j = 0; j < D4; j++) {
            int c = j & 31;
            ulonglong2 yv = sy[j * BN + (lane ^ c)];
            ffma2(ny, yv.x, yv.x); ffma2(ny, yv.y, yv.y);
            #pragma unroll
            for (int r = 0; r < RPW; r++) {
                ulonglong2 xv = sx[(warp * RPW + r) * D4 + j];  // broadcast
                ffma2(s[r], xv.x, yv.x); ffma2(s[r], xv.y, yv.y);
            }
        }

        bool vmask = (n0 + lane) < n_end;
        float t0, t1;
        unpack2(ny, t0, t1); float dn = t0 + t1;

        // ---- online softmax (RPW rows), p in registers ----
        float p0[RPW];
        #pragma unroll
        for (int r = 0; r < RPW; r++) {
            float slo, shi;
            unpack2(s[r], slo, shi);
            float lg = vmask ? fmaf(al[r], slo + shi, -be[r] * dn) : -INFINITY;

            float mt = lg;
            #pragma unroll
            for (int off = 16; off > 0; off >>= 1)
                mt = fmaxf(mt, __shfl_xor_sync(0xffffffffu, mt, off));
            if (mt > mrun[r]) {      // rescale only when max moves (warp-uniform)
                float sc = __expf(mrun[r] - mt);   // first tile: exp(-inf)=0
                lrun[r] *= sc;
                u64 scp = pack2(sc, sc);
                #pragma unroll
                for (int i = 0; i < 8; i++) fmul2(acc[r][i], scp);
                mrun[r] = mt;
            }
            p0[r] = __expf(lg - mrun[r]);
            float ps = p0[r];
            #pragma unroll
            for (int off = 16; off > 0; off >>= 1)
                ps += __shfl_xor_sync(0xffffffffu, ps, off);
            lrun[r] += ps;
        }

        // ---- PV: p broadcast via shfl (lane nn owns key n0+nn) ----
        #pragma unroll 2
        for (int nn = 0; nn < BN; nn++) {
            u64 pp[RPW];
            #pragma unroll
            for (int r = 0; r < RPW; r++) {
                float pv = __shfl_sync(0xffffffffu, p0[r], nn);
                pp[r] = pack2(pv, pv);
            }
            #pragma unroll
            for (int k = 0; k < 4; k++) {
                int j = lane + 32 * k;
                ulonglong2 yv = sy[j * BN + (nn ^ (j & 31))];
                #pragma unroll
                for (int r = 0; r < RPW; r++) {
                    ffma2(acc[r][2*k],   pp[r], yv.x);
                    ffma2(acc[r][2*k+1], pp[r], yv.y);
                }
            }
        }
    }

    // ---- write per-(row,split) partials (skip rows >= B) ----
    {
        ulonglong2* gacc2 = (ulonglong2*)g_acc;
        #pragma unroll
        for (int r = 0; r < RPW; r++) {
            int row = r0 + warp * RPW + r;
            if (row < B_SZ) {
                size_t base = ((size_t)row * NSPLIT + split) * D4;
                #pragma unroll
                for (int k = 0; k < 4; k++)
                    gacc2[base + lane + 32 * k] =
                        make_ulonglong2(acc[r][2*k], acc[r][2*k+1]);
                if (lane == 0) {
                    g_ml[(row * NSPLIT + split) * 2 + 0] = mrun[r];
                    g_ml[(row * NSPLIT + split) * 2 + 1] = lrun[r];
                }
            }
        }
    }

    // ---- last-CTA combine epilogue ----
    __threadfence();
    __syncthreads();
    if (tid == 0) {
        int old = atomicAdd(&g_cnt[rb], 1);
        s_last = (old == NSPLIT - 1) ? 1 : 0;
    }
    __syncthreads();
    if (!s_last) return;
    __threadfence();

    // 384 threads: 8 threads/row, 48 rows/pass, 2 passes cover BM=60
    #pragma unroll
    for (int pass = 0; pass < 2; pass++) {
        int rl = pass * 48 + (tid >> 3);
        int row = r0 + rl;
        if (rl < BM && row < B_SZ) {
            int jc = tid & 7;
            float ms[NSPLIT], ls[NSPLIT];
            float M = -INFINITY;
            #pragma unroll
            for (int s = 0; s < NSPLIT; s++) {
                float2 ml = __ldcg((const float2*)&g_ml[(row * NSPLIT + s) * 2]);
                ms[s] = ml.x; ls[s] = ml.y;
                M = fmaxf(M, ms[s]);
            }
            float w[NSPLIT], L = 0.f;
            #pragma unroll
            for (int s = 0; s < NSPLIT; s++) {
                w[s] = __expf(ms[s] - M);
                L = fmaf(w[s], ls[s], L);
            }
            float a = t[row], b = 1.f - a;
            float c1 = -1.f / b;
            float c2 = (1.f + a / b) / L;

            const float4* gacc4 = (const float4*)g_acc;
            #pragma unroll 4
            for (int q = 0; q < 16; q++) {
                int j = jc + 8 * q;
                float4 ws = make_float4(0.f, 0.f, 0.f, 0.f);
                #pragma unroll
                for (int s = 0; s < NSPLIT; s++) {
                    float4 v = __ldcg(&gacc4[((size_t)row * NSPLIT + s) * D4 + j]);
                    ws.x = fmaf(w[s], v.x, ws.x); ws.y = fmaf(w[s], v.y, ws.y);
                    ws.z = fmaf(w[s], v.z, ws.z); ws.w = fmaf(w[s], v.w, ws.w);
                }
                float4 xv = x4[(size_t)row * D4 + j];
                float4 o;
                o.x = fmaf(c1, xv.x, c2 * ws.x);
                o.y = fmaf(c1, xv.y, c2 * ws.y);
                o.z = fmaf(c1, xv.z, c2 * ws.z);
                o.w = fmaf(c1, xv.w, c2 * ws.w);
                ((float4*)out)[(size_t)row * D4 + j] = o;
            }
        }
    }
    __syncthreads();
    if (tid == 0) g_cnt[rb] = 0;   // reset for next graph replay
}

// ---------------------------------------------------------------------------
extern "C" void kernel_launch(void* const* d_in, const int* in_sizes, int n_in,
                              void* d_out, int out_size)
{
    const float* x = (const float*)d_in[0];   // x_t (1024,512)
    const float* t = (const float*)d_in[1];   // t (1024,)
    const float* y = (const float*)d_in[2];   // dataset (100000,512)
    float* out = (float*)d_out;

    cudaFuncSetAttribute(flash_kernel,
                         cudaFuncAttributeMaxDynamicSharedMemorySize, SMEM_BYTES);
    flash_kernel<<<dim3(NRB, NSPLIT), THREADS, SMEM_BYTES>>>(x, t, y, out);
}

// round 10
// speedup vs baseline: 1.1786x; 1.1764x over previous
#include <cuda_runtime.h>
#include <math.h>

// Problem shapes (fixed)
#define B_SZ 1024
#define N_SZ 100000
#define D_SZ 512
#define D4   128               // float4 per row
#define RPW  6                 // rows per warp
#define NWARP 8
#define THREADS (NWARP*32)     // 256
#define BM   (NWARP*RPW)       // 48 rows per CTA
#define BN   64                // keys per tile (2 per lane)
#define FH   64                // float4 per half-tile (D split in two)
#define NSPLIT 13
#define SPL  7693              // ceil(N/NSPLIT)
#define NRB  22                // ceil(1024/48)

#define SX_F4   (BM*D4)                    // 6144 float4 = 96KB
#define BUF_F4  (FH*BN)                    // 4096 float4 = 64KB
#define SMEM_BYTES ((SX_F4 + 2*BUF_F4)*16) // 229376 <= 232448

// Scratch
__device__ float g_ml[B_SZ * NSPLIT * 2];
__device__ float g_acc[(size_t)B_SZ * NSPLIT * D_SZ];
__device__ int   g_cnt[NRB];   // zero-init; last CTA resets after use

typedef unsigned long long u64;
__device__ __forceinline__ u64 pack2(float a, float b) {
    u64 r; asm("mov.b64 %0,{%1,%2};" : "=l"(r) : "f"(a), "f"(b)); return r;
}
__device__ __forceinline__ void unpack2(u64 v, float& a, float& b) {
    asm("mov.b64 {%0,%1},%2;" : "=f"(a), "=f"(b) : "l"(v));
}
__device__ __forceinline__ void ffma2(u64& d, u64 a, u64 b) {
    asm("fma.rn.f32x2 %0,%1,%2,%0;" : "+l"(d) : "l"(a), "l"(b));
}
__device__ __forceinline__ void fmul2(u64& d, u64 a) {
    asm("mul.rn.f32x2 %0,%0,%1;" : "+l"(d) : "l"(a));
}
__device__ __forceinline__ void cp16(unsigned dst, const void* src) {
    asm volatile("cp.async.cg.shared.global [%0], [%1], 16;" :: "r"(dst), "l"(src));
}
#define CP_COMMIT() asm volatile("cp.async.commit_group;")
#define CP_WAIT(n)  asm volatile("cp.async.wait_group %0;" :: "n"(n))

// load one D-half of a key tile into a buffer (swizzled).
// float4 (n, f_local) stored at buf[f*BN + (n ^ f)]  (f, n in [0,64))
__device__ __forceinline__ void load_half(unsigned buf_u, const float4* y4g,
                                          int n0, int fbase, int tid)
{
    #pragma unroll
    for (int q = 0; q < BUF_F4 / THREADS; q++) {
        int i = q * THREADS + tid;
        int n = i >> 6, f = i & 63;
        int nc = min(n0 + n, N_SZ - 1);            // clamp; masked later
        cp16(buf_u + (unsigned)(f * BN + (n ^ f)) * 16,
             &y4g[(size_t)nc * D4 + fbase + f]);
    }
}

// ---------------------------------------------------------------------------
// Fused flash kernel: QK (+key norms) -> online softmax -> PV, with the
// key tile D-split into two 64KB halves that are double-buffered via
// cp.async so tile loads overlap compute.
// logit'[b][n] = (a/b^2)*<x_b,y_n> - (a^2/(2b^2))*||y_n||^2
// v = (-1/b) x + (1 + a/b) * softmax-weighted dataset
// ---------------------------------------------------------------------------
__global__ __launch_bounds__(THREADS, 1) void flash_kernel(
    const float* __restrict__ x, const float* __restrict__ t,
    const float* __restrict__ y, float* __restrict__ out)
{
    extern __shared__ char smem_raw[];
    ulonglong2* sx   = (ulonglong2*)smem_raw;     // BM*D4 float4
    ulonglong2* bufA = sx + SX_F4;                // FH*BN float4 (f in [0,64))
    ulonglong2* bufB = bufA + BUF_F4;             // FH*BN float4 (f in [64,128))
    __shared__ int s_last;

    const int tid  = threadIdx.x;
    const int lane = tid & 31;
    const int warp = tid >> 5;
    const int rb      = blockIdx.x;
    const int r0      = rb * BM;
    const int split   = blockIdx.y;
    const int n_begin = split * SPL;
    const int n_end   = min(n_begin + SPL, N_SZ);

    const unsigned sx_u = (unsigned)__cvta_generic_to_shared(sx);
    const unsigned bA_u = (unsigned)__cvta_generic_to_shared(bufA);
    const unsigned bB_u = (unsigned)__cvta_generic_to_shared(bufB);
    const float4* x4  = (const float4*)x;
    const float4* y4g = (const float4*)y;

    // Prologue: group1 = {x tile, tile0 half0 -> A}; group2 = {tile0 half1 -> B}
    for (int i = tid; i < SX_F4; i += THREADS) {
        int rc = min(r0 + (i >> 7), B_SZ - 1);
        cp16(sx_u + i * 16, &x4[(size_t)rc * D4 + (i & 127)]);
    }
    load_half(bA_u, y4g, n_begin, 0, tid);
    CP_COMMIT();
    load_half(bB_u, y4g, n_begin, FH, tid);
    CP_COMMIT();

    // per-row coefficients
    float al[RPW], be[RPW];
    #pragma unroll
    for (int r = 0; r < RPW; r++) {
        int row = min(r0 + warp * RPW + r, B_SZ - 1);
        float tv = t[row];
        float a = tv, b = 1.f - tv;
        al[r] = a / (b * b);
        be[r] = a * a / (2.f * b * b);
    }

    float mrun[RPW], lrun[RPW];
    u64 acc[RPW][8];
    #pragma unroll
    for (int r = 0; r < RPW; r++) {
        mrun[r] = -INFINITY; lrun[r] = 0.f;
        #pragma unroll
        for (int i = 0; i < 8; i++) acc[r][i] = 0ull;
    }

    const ulonglong2* sx_w = sx + (warp * RPW) * D4;
    const int nl0 = lane, nl1 = lane + 32;

    for (int n0 = n_begin; n0 < n_end; n0 += BN) {
        const bool more = (n0 + BN) < n_end;

        u64 s[RPW][2];
        #pragma unroll
        for (int r = 0; r < RPW; r++) { s[r][0] = 0ull; s[r][1] = 0ull; }
        u64 ny0 = 0ull, ny1 = 0ull;

        // ---- QK half 0 (bufA, f in [0,64)) ----
        CP_WAIT(1);            // A (and x on first iter) complete
        __syncthreads();
        #pragma unroll 2
        for (int f = 0; f < FH; f++) {
            ulonglong2 yv0 = bufA[f * BN + (nl0 ^ f)];
            ulonglong2 yv1 = bufA[f * BN + (nl1 ^ f)];
            ffma2(ny0, yv0.x, yv0.x); ffma2(ny0, yv0.y, yv0.y);
            ffma2(ny1, yv1.x, yv1.x); ffma2(ny1, yv1.y, yv1.y);
            #pragma unroll
            for (int r = 0; r < RPW; r++) {
                ulonglong2 xv = sx_w[r * D4 + f];          // broadcast
                ffma2(s[r][0], xv.x, yv0.x); ffma2(s[r][0], xv.y, yv0.y);
                ffma2(s[r][1], xv.x, yv1.x); ffma2(s[r][1], xv.y, yv1.y);
            }
        }

        // ---- QK half 1 (bufB, f in [64,128)) ----
        CP_WAIT(0);            // B complete
        __syncthreads();
        #pragma unroll 2
        for (int f = 0; f < FH; f++) {
            ulonglong2 yv0 = bufB[f * BN + (nl0 ^ f)];
            ulonglong2 yv1 = bufB[f * BN + (nl1 ^ f)];
            ffma2(ny0, yv0.x, yv0.x); ffma2(ny0, yv0.y, yv0.y);
            ffma2(ny1, yv1.x, yv1.x); ffma2(ny1, yv1.y, yv1.y);
            #pragma unroll
            for (int r = 0; r < RPW; r++) {
                ulonglong2 xv = sx_w[r * D4 + FH + f];     // broadcast
                ffma2(s[r][0], xv.x, yv0.x); ffma2(s[r][0], xv.y, yv0.y);
                ffma2(s[r][1], xv.x, yv1.x); ffma2(s[r][1], xv.y, yv1.y);
            }
        }

        // ---- logits + online softmax ----
        bool v0 = (n0 + nl0) < n_end;
        bool v1 = (n0 + nl1) < n_end;
        float t0, t1;
        unpack2(ny0, t0, t1); float dn0 = t0 + t1;
        unpack2(ny1, t0, t1); float dn1 = t0 + t1;

        float p0[RPW], p1[RPW];
        #pragma unroll
        for (int r = 0; r < RPW; r++) {
            float slo, shi;
            unpack2(s[r][0], slo, shi);
            float lg0 = v0 ? fmaf(al[r], slo + shi, -be[r] * dn0) : -INFINITY;
            unpack2(s[r][1], slo, shi);
            float lg1 = v1 ? fmaf(al[r], slo + shi, -be[r] * dn1) : -INFINITY;

            float mt = fmaxf(lg0, lg1);
            #pragma unroll
            for (int off = 16; off > 0; off >>= 1)
                mt = fmaxf(mt, __shfl_xor_sync(0xffffffffu, mt, off));
            if (mt > mrun[r]) {           // warp-uniform
                float sc = __expf(mrun[r] - mt);   // first tile: 0
                lrun[r] *= sc;
                u64 scp = pack2(sc, sc);
                #pragma unroll
                for (int i = 0; i < 8; i++) fmul2(acc[r][i], scp);
                mrun[r] = mt;
            }
            p0[r] = __expf(lg0 - mrun[r]);
            p1[r] = __expf(lg1 - mrun[r]);
            float ps = p0[r] + p1[r];
            #pragma unroll
            for (int off = 16; off > 0; off >>= 1)
                ps += __shfl_xor_sync(0xffffffffu, ps, off);
            lrun[r] += ps;
        }

        // ---- PV on bufA (j = lane, lane+32) ----
        #pragma unroll 2
        for (int nn = 0; nn < 32; nn++) {
            u64 ppa[RPW], ppb[RPW];
            #pragma unroll
            for (int r = 0; r < RPW; r++) {
                float pa = __shfl_sync(0xffffffffu, p0[r], nn);
                float pb = __shfl_sync(0xffffffffu, p1[r], nn);
                ppa[r] = pack2(pa, pa);
                ppb[r] = pack2(pb, pb);
            }
            #pragma unroll
            for (int k = 0; k < 2; k++) {
                int f = lane + 32 * k;
                ulonglong2 ya = bufA[f * BN + (nn ^ f)];
                ulonglong2 yb = bufA[f * BN + ((nn + 32) ^ f)];
                #pragma unroll
                for (int r = 0; r < RPW; r++) {
                    ffma2(acc[r][2*k],   ppa[r], ya.x);
                    ffma2(acc[r][2*k+1], ppa[r], ya.y);
                    ffma2(acc[r][2*k],   ppb[r], yb.x);
                    ffma2(acc[r][2*k+1], ppb[r], yb.y);
                }
            }
        }
        __syncthreads();                   // everyone done with A
        if (more) { load_half(bA_u, y4g, n0 + BN, 0, tid); }
        CP_COMMIT();                       // group: next half0 -> A

        // ---- PV on bufB (j = lane+64, lane+96) ----
        #pragma unroll 2
        for (int nn = 0; nn < 32; nn++) {
            u64 ppa[RPW], ppb[RPW];
            #pragma unroll
            for (int r = 0; r < RPW; r++) {
                float pa = __shfl_sync(0xffffffffu, p0[r], nn);
                float pb = __shfl_sync(0xffffffffu, p1[r], nn);
                ppa[r] = pack2(pa, pa);
                ppb[r] = pack2(pb, pb);
            }
            #pragma unroll
            for (int k = 0; k < 2; k++) {
                int f = lane + 32 * k;
                ulonglong2 ya = bufB[f * BN + (nn ^ f)];
                ulonglong2 yb = bufB[f * BN + ((nn + 32) ^ f)];
                #pragma unroll
                for (int r = 0; r < RPW; r++) {
                    ffma2(acc[r][4+2*k],   ppa[r], ya.x);
                    ffma2(acc[r][4+2*k+1], ppa[r], ya.y);
                    ffma2(acc[r][4+2*k],   ppb[r], yb.x);
                    ffma2(acc[r][4+2*k+1], ppb[r], yb.y);
                }
            }
        }
        __syncthreads();                   // everyone done with B
        if (more) { load_half(bB_u, y4g, n0 + BN, FH, tid); }
        CP_COMMIT();                       // group: next half1 -> B
    }

    // ---- write per-(row,split) partials (skip rows >= B) ----
    {
        ulonglong2* gacc2 = (ulonglong2*)g_acc;
        #pragma unroll
        for (int r = 0; r < RPW; r++) {
            int row = r0 + warp * RPW + r;
            if (row < B_SZ) {
                size_t base = ((size_t)row * NSPLIT + split) * D4;
                #pragma unroll
                for (int k = 0; k < 4; k++)
                    gacc2[base + lane + 32 * k] =
                        make_ulonglong2(acc[r][2*k], acc[r][2*k+1]);
                if (lane == 0) {
                    g_ml[(row * NSPLIT + split) * 2 + 0] = mrun[r];
                    g_ml[(row * NSPLIT + split) * 2 + 1] = lrun[r];
                }
            }
        }
    }

    // ---- last-CTA combine epilogue ----
    __threadfence();
    __syncthreads();
    if (tid == 0) {
        int old = atomicAdd(&g_cnt[rb], 1);
        s_last = (old == NSPLIT - 1) ? 1 : 0;
    }
    __syncthreads();
    if (!s_last) return;
    __threadfence();

    // 256 threads: 8 threads/row, 32 rows/pass, 2 passes cover BM=48
    #pragma unroll
    for (int pass = 0; pass < 2; pass++) {
        int rl = pass * 32 + (tid >> 3);
        int row = r0 + rl;
        if (rl < BM && row < B_SZ) {
            int jc = tid & 7;
            float ms[NSPLIT], ls[NSPLIT];
            float M = -INFINITY;
            #pragma unroll
            for (int s = 0; s < NSPLIT; s++) {
                float2 ml = __ldcg((const float2*)&g_ml[(row * NSPLIT + s) * 2]);
                ms[s] = ml.x; ls[s] = ml.y;
                M = fmaxf(M, ms[s]);
            }
            float w[NSPLIT], L = 0.f;
            #pragma unroll
            for (int s = 0; s < NSPLIT; s++) {
                w[s] = __expf(ms[s] - M);
                L = fmaf(w[s], ls[s], L);
            }
            float a = t[row], b = 1.f - a;
            float c1 = -1.f / b;
            float c2 = (1.f + a / b) / L;

            const float4* gacc4 = (const float4*)g_acc;
            #pragma unroll 4
            for (int q = 0; q < 16; q++) {
                int j = jc + 8 * q;
                float4 ws = make_float4(0.f, 0.f, 0.f, 0.f);
                #pragma unroll
                for (int s = 0; s < NSPLIT; s++) {
                    float4 v = __ldcg(&gacc4[((size_t)row * NSPLIT + s) * D4 + j]);
                    ws.x = fmaf(w[s], v.x, ws.x); ws.y = fmaf(w[s], v.y, ws.y);
                    ws.z = fmaf(w[s], v.z, ws.z); ws.w = fmaf(w[s], v.w, ws.w);
                }
                float4 xv = x4[(size_t)row * D4 + j];
                float4 o;
                o.x = fmaf(c1, xv.x, c2 * ws.x);
                o.y = fmaf(c1, xv.y, c2 * ws.y);
                o.z = fmaf(c1, xv.z, c2 * ws.z);
                o.w = fmaf(c1, xv.w, c2 * ws.w);
                ((float4*)out)[(size_t)row * D4 + j] = o;
            }
        }
    }
    __syncthreads();
    if (tid == 0) g_cnt[rb] = 0;   // reset for next graph replay
}

// ---------------------------------------------------------------------------
extern "C" void kernel_launch(void* const* d_in, const int* in_sizes, int n_in,
                              void* d_out, int out_size)
{
    const float* x = (const float*)d_in[0];   // x_t (1024,512)
    const float* t = (const float*)d_in[1];   // t (1024,)
    const float* y = (const float*)d_in[2];   // dataset (100000,512)
    float* out = (float*)d_out;

    cudaFuncSetAttribute(flash_kernel,
                         cudaFuncAttributeMaxDynamicSharedMemorySize, SMEM_BYTES);
    flash_kernel<<<dim3(NRB, NSPLIT), THREADS, SMEM_BYTES>>>(x, t, y, out);
}

// round 11
// speedup vs baseline: 1.6359x; 1.3881x over previous
#include <cuda_runtime.h>
#include <math.h>

// Problem shapes (fixed)
#define B_SZ 1024
#define N_SZ 100000
#define D_SZ 512
#define NPAD 100096              // 782 * 128 (padded key count)
#define NT_M 8                   // 1024/128 m-tiles
#define NT_N 782                 // NPAD/128 n-tiles

#define BK   32                  // k-chunk
#define AST  132                 // smem row stride (floats), transposed tiles
#define BST3 128                 // K3 B smem row stride (floats)

// K3 split-K over keys: 25 exact splits of 4000, chunks of 32 (125 exact)
#define NSPL3 25
#define SPL3  4000
#define CH3   125

typedef unsigned long long u64;

// ---------------- scratch (static device globals; zero-initialized) --------
__device__ float g_xs[B_SZ * D_SZ];            // al-scaled x
__device__ float g_be[B_SZ], g_c1[B_SZ], g_c2[B_SZ];
__device__ float g_dsn[NPAD];                  // pad stays 0
__device__ float g_m[B_SZ], g_L[B_SZ];
__device__ float g_logit[(size_t)B_SZ * NPAD]; // holds P after pexp_kernel
__device__ float g_pv[(size_t)NSPL3 * B_SZ * D_SZ];

// ---------------- packed f32x2 helpers ------------------------------------
__device__ __forceinline__ u64 pack2(float a, float b) {
    u64 r; asm("mov.b64 %0,{%1,%2};" : "=l"(r) : "f"(a), "f"(b)); return r;
}
__device__ __forceinline__ void unpack2(u64 v, float& a, float& b) {
    asm("mov.b64 {%0,%1},%2;" : "=f"(a), "=f"(b) : "l"(v));
}
__device__ __forceinline__ void ffma2(u64& d, u64 a, u64 b) {
    asm("fma.rn.f32x2 %0,%1,%2,%0;" : "+l"(d) : "l"(a), "l"(b));
}
__device__ __forceinline__ void cp16(unsigned dst, const void* src) {
    asm volatile("cp.async.cg.shared.global [%0], [%1], 16;" :: "r"(dst), "l"(src));
}
#define CP_COMMIT() asm volatile("cp.async.commit_group;")
#define CP_WAIT0()  asm volatile("cp.async.wait_group 0;")

// 8x8 per-thread FFMA2 microkernel step: c[i][j] covers rows ty8+i, col-pairs tx8+2j
__device__ __forceinline__ void mm_step(const float* Ak, const float* Bk,
                                        int ty8, int tx8, u64 (&c)[8][4]) {
    float4 a0 = *(const float4*)(Ak + ty8);
    float4 a1 = *(const float4*)(Ak + ty8 + 4);
    float4 b0 = *(const float4*)(Bk + tx8);
    float4 b1 = *(const float4*)(Bk + tx8 + 4);
    u64 bp0 = pack2(b0.x, b0.y), bp1 = pack2(b0.z, b0.w);
    u64 bp2 = pack2(b1.x, b1.y), bp3 = pack2(b1.z, b1.w);
    float av[8] = {a0.x, a0.y, a0.z, a0.w, a1.x, a1.y, a1.z, a1.w};
    #pragma unroll
    for (int i = 0; i < 8; i++) {
        u64 ad = pack2(av[i], av[i]);
        ffma2(c[i][0], ad, bp0);
        ffma2(c[i][1], ad, bp1);
        ffma2(c[i][2], ad, bp2);
        ffma2(c[i][3], ad, bp3);
    }
}

// ---------------------------------------------------------------------------
// K0 prep: dsn[n]=||y_n||^2 (blocks 0..12499, 8 rows each); coeffs (block
// 12500); x' = (a/b^2) * x (blocks 12501..12564)
// ---------------------------------------------------------------------------
__global__ void prep_kernel(const float* __restrict__ x,
                            const float* __restrict__ t,
                            const float* __restrict__ y)
{
    int bid = blockIdx.x, tid = threadIdx.x;
    if (bid < 12500) {
        int warp = tid >> 5, lane = tid & 31;
        int n = bid * 8 + warp;
        const float4* y4 = (const float4*)y;
        float s = 0.f;
        #pragma unroll
        for (int k = 0; k < 4; k++) {
            float4 v = y4[(size_t)n * 128 + lane + 32 * k];
            s = fmaf(v.x, v.x, fmaf(v.y, v.y, fmaf(v.z, v.z, fmaf(v.w, v.w, s))));
        }
        #pragma unroll
        for (int off = 16; off > 0; off >>= 1)
            s += __shfl_xor_sync(0xffffffffu, s, off);
        if (lane == 0) g_dsn[n] = s;
    } else if (bid == 12500) {
        #pragma unroll
        for (int q = 0; q < 4; q++) {
            int r = tid + 256 * q;
            float a = t[r], b = 1.f - a;
            g_be[r] = a * a / (2.f * b * b);
            g_c1[r] = -1.f / b;
            g_c2[r] = 1.f + a / b;
        }
    } else {
        int base = (bid - 12501) * 2048;
        const float4* x4 = (const float4*)x;
        float4* xs4 = (float4*)g_xs;
        #pragma unroll
        for (int q = 0; q < 8; q++) {
            int i = base + tid + 256 * q;
            int row = i >> 7;
            float tv = t[row], b = 1.f - tv;
            float al = tv / (b * b);
            float4 v = x4[i];
            v.x *= al; v.y *= al; v.z *= al; v.w *= al;
            xs4[i] = v;
        }
    }
}

// ---------------------------------------------------------------------------
// K1: QK GEMM. C = X' @ Y^T, epilogue lg = c - be[m]*dsn[n] -> g_logit.
// 128x128 tile per CTA, 256 threads, 8x8 per thread, k-chunks of 32.
// ---------------------------------------------------------------------------
__global__ __launch_bounds__(256) void qk_kernel(const float* __restrict__ y)
{
    extern __shared__ float sm[];
    float* As = sm;                    // [2][BK][AST] (k-major, transposed)
    float* Bs = sm + 2 * BK * AST;     // [2][BK][AST]

    const int tid = threadIdx.x;
    const int tx = tid & 15, ty = tid >> 4;
    const int ty8 = ty * 8, tx8 = tx * 8;
    const int m0 = blockIdx.x * 128;
    const int n0 = blockIdx.y * 128;

    const float4* xa = (const float4*)g_xs;
    const float4* ya = (const float4*)y;

    u64 c[8][4];
    #pragma unroll
    for (int i = 0; i < 8; i++)
        #pragma unroll
        for (int j = 0; j < 4; j++) c[i][j] = 0ull;

    float4 ra[4], rb[4];

    // chunk loaders: f4 index i -> row (i>>3), f4-in-chunk (i&7)
    #define LDG_AB(kc) { int kf = (kc) * 8;                                          \
        _Pragma("unroll") for (int q = 0; q < 4; q++) { int i = tid + 256 * q;       \
            ra[q] = xa[(size_t)(m0 + (i >> 3)) * 128 + kf + (i & 7)]; }              \
        _Pragma("unroll") for (int q = 0; q < 4; q++) { int i = tid + 256 * q;       \
            int nc = min(n0 + (i >> 3), N_SZ - 1);                                   \
            rb[q] = ya[(size_t)nc * 128 + kf + (i & 7)]; } }
    #define STS_AB(bf) { float* Ad = As + (bf) * BK * AST; float* Bd = Bs + (bf) * BK * AST; \
        _Pragma("unroll") for (int q = 0; q < 4; q++) { int i = tid + 256 * q;       \
            int m = i >> 3; int k4 = (i & 7) * 4;                                    \
            Ad[(k4+0)*AST+m] = ra[q].x; Ad[(k4+1)*AST+m] = ra[q].y;                  \
            Ad[(k4+2)*AST+m] = ra[q].z; Ad[(k4+3)*AST+m] = ra[q].w;                  \
            Bd[(k4+0)*AST+m] = rb[q].x; Bd[(k4+1)*AST+m] = rb[q].y;                  \
            Bd[(k4+2)*AST+m] = rb[q].z; Bd[(k4+3)*AST+m] = rb[q].w; } }

    LDG_AB(0);
    STS_AB(0);
    __syncthreads();

    for (int kc = 0; kc < 16; kc++) {
        int cur = kc & 1;
        if (kc < 15) LDG_AB(kc + 1);
        const float* Ab = As + cur * BK * AST;
        const float* Bb = Bs + cur * BK * AST;
        #pragma unroll 8
        for (int k = 0; k < BK; k++)
            mm_step(Ab + k * AST, Bb + k * AST, ty8, tx8, c);
        if (kc < 15) STS_AB(cur ^ 1);
        __syncthreads();
    }
    #undef LDG_AB
    #undef STS_AB

    // epilogue: lg = c - be[m]*dsn[n]
    float bev[8], dsv[8];
    #pragma unroll
    for (int i = 0; i < 8; i++) bev[i] = g_be[m0 + ty8 + i];
    #pragma unroll
    for (int jc = 0; jc < 8; jc++) dsv[jc] = g_dsn[n0 + tx8 + jc];

    #pragma unroll
    for (int i = 0; i < 8; i++) {
        size_t rbase = (size_t)(m0 + ty8 + i) * NPAD + n0 + tx8;
        #pragma unroll
        for (int j = 0; j < 4; j++) {
            float v0, v1;
            unpack2(c[i][j], v0, v1);
            float2 o;
            o.x = fmaf(-bev[i], dsv[2*j],     v0);
            o.y = fmaf(-bev[i], dsv[2*j + 1], v1);
            *(float2*)&g_logit[rbase + 2*j] = o;
        }
    }
}

// ---------------------------------------------------------------------------
// K2a: row max over logits (n < 100000)
// ---------------------------------------------------------------------------
__global__ void rowmax_kernel()
{
    int row = blockIdx.x, tid = threadIdx.x;
    const float4* rp = (const float4*)(g_logit + (size_t)row * NPAD);
    float m = -1e30f;
    for (int c = tid; c < N_SZ / 4; c += 256) {
        float4 v = rp[c];
        m = fmaxf(m, fmaxf(fmaxf(v.x, v.y), fmaxf(v.z, v.w)));
    }
    #pragma unroll
    for (int off = 16; off > 0; off >>= 1)
        m = fmaxf(m, __shfl_xor_sync(0xffffffffu, m, off));
    __shared__ float red[8];
    if ((tid & 31) == 0) red[tid >> 5] = m;
    __syncthreads();
    if (tid == 0) {
        float mm = red[0];
        #pragma unroll
        for (int w = 1; w < 8; w++) mm = fmaxf(mm, red[w]);
        g_m[row] = mm;
    }
}

// ---------------------------------------------------------------------------
// K2b: P = exp(lg - m) in-place; L = sum(P)
// ---------------------------------------------------------------------------
__global__ void pexp_kernel()
{
    int row = blockIdx.x, tid = threadIdx.x;
    float4* rp = (float4*)(g_logit + (size_t)row * NPAD);
    float mr = g_m[row];
    float l = 0.f;
    for (int c = tid; c < N_SZ / 4; c += 256) {
        float4 v = rp[c];
        v.x = __expf(v.x - mr); v.y = __expf(v.y - mr);
        v.z = __expf(v.z - mr); v.w = __expf(v.w - mr);
        l += (v.x + v.y) + (v.z + v.w);
        rp[c] = v;
    }
    #pragma unroll
    for (int off = 16; off > 0; off >>= 1)
        l += __shfl_xor_sync(0xffffffffu, l, off);
    __shared__ float red[8];
    if ((tid & 31) == 0) red[tid >> 5] = l;
    __syncthreads();
    if (tid == 0) {
        float s = red[0];
        #pragma unroll
        for (int w = 1; w < 8; w++) s += red[w];
        g_L[row] = s;
    }
}

// ---------------------------------------------------------------------------
// K3: PV GEMM. pv[m,d] = sum_n P[m,n] * Y[n,d], split-K over 25 splits of
// 4000 keys (125 exact chunks of 32). A = P (transposed staging), B = Y
// (direct cp.async staging). Partials -> g_pv[split].
// ---------------------------------------------------------------------------
__global__ __launch_bounds__(256) void pv_kernel(const float* __restrict__ y)
{
    extern __shared__ float sm[];
    float* As = sm;                    // [2][BK][AST]  (P, k(n)-major)
    float* Bs = sm + 2 * BK * AST;     // [2][BK][BST3] (Y, k(n)-major direct)

    const int tid = threadIdx.x;
    const int tx = tid & 15, ty = tid >> 4;
    const int ty8 = ty * 8, tx8 = tx * 8;
    const int mt = blockIdx.x >> 2, dt = blockIdx.x & 3;
    const int m0 = mt * 128, d0 = dt * 128;
    const int split = blockIdx.y;
    const int nbase = split * SPL3;

    const float4* pl4 = (const float4*)g_logit;   // now holds P
    const float4* ya  = (const float4*)y;
    const unsigned bs_u = (unsigned)__cvta_generic_to_shared(Bs);

    u64 c[8][4];
    #pragma unroll
    for (int i = 0; i < 8; i++)
        #pragma unroll
        for (int j = 0; j < 4; j++) c[i][j] = 0ull;

    float4 pa[4];

    #define LDG_A(ch) { int nf4 = (nbase + (ch) * 32) >> 2;                          \
        _Pragma("unroll") for (int q = 0; q < 4; q++) { int i = tid + 256 * q;       \
            pa[q] = pl4[(size_t)(m0 + (i >> 3)) * (NPAD/4) + nf4 + (i & 7)]; } }
    #define STS_A(bf) { float* Ad = As + (bf) * BK * AST;                            \
        _Pragma("unroll") for (int q = 0; q < 4; q++) { int i = tid + 256 * q;       \
            int m = i >> 3; int k4 = (i & 7) * 4;                                    \
            Ad[(k4+0)*AST+m] = pa[q].x; Ad[(k4+1)*AST+m] = pa[q].y;                  \
            Ad[(k4+2)*AST+m] = pa[q].z; Ad[(k4+3)*AST+m] = pa[q].w; } }
    #define CP_B(ch, bf) { int nb = nbase + (ch) * 32;                               \
        _Pragma("unroll") for (int q = 0; q < 4; q++) { int i = tid + 256 * q;       \
            int k = i >> 5, d4 = i & 31;                                             \
            cp16(bs_u + (unsigned)(((bf) * BK * BST3 + k * BST3 + d4 * 4) * 4),      \
                 &ya[(size_t)(nb + k) * 128 + (d0 >> 2) + d4]); } }

    LDG_A(0);
    CP_B(0, 0); CP_COMMIT();
    STS_A(0);
    CP_WAIT0();
    __syncthreads();

    for (int ch = 0; ch < CH3; ch++) {
        int cur = ch & 1;
        if (ch < CH3 - 1) { LDG_A(ch + 1); CP_B(ch + 1, cur ^ 1); CP_COMMIT(); }
        const float* Ab = As + cur * BK * AST;
        const float* Bb = Bs + cur * BK * BST3;
        #pragma unroll 8
        for (int k = 0; k < BK; k++)
            mm_step(Ab + k * AST, Bb + k * BST3, ty8, tx8, c);
        if (ch < CH3 - 1) { STS_A(cur ^ 1); CP_WAIT0(); }
        __syncthreads();
    }
    #undef LDG_A
    #undef STS_A
    #undef CP_B

    // write partials
    #pragma unroll
    for (int i = 0; i < 8; i++) {
        size_t rbase = ((size_t)split * B_SZ + m0 + ty8 + i) * D_SZ + d0 + tx8;
        #pragma unroll
        for (int j = 0; j < 4; j++) {
            float v0, v1;
            unpack2(c[i][j], v0, v1);
            *(float2*)&g_pv[rbase + 2*j] = make_float2(v0, v1);
        }
    }
}

// ---------------------------------------------------------------------------
// K4: combine splits + final affine. v = c1*x + (c2/L) * sum_s pv[s]
// ---------------------------------------------------------------------------
__global__ void combine_kernel(const float* __restrict__ x,
                               float* __restrict__ out)
{
    int row = blockIdx.x, tid = threadIdx.x;   // 128 threads, one float4 each
    const float4* pv4 = (const float4*)g_pv;
    float4 s = make_float4(0.f, 0.f, 0.f, 0.f);
    #pragma unroll
    for (int sp = 0; sp < NSPL3; sp++) {
        float4 v = pv4[((size_t)sp * B_SZ + row) * 128 + tid];
        s.x += v.x; s.y += v.y; s.z += v.z; s.w += v.w;
    }
    float c1 = g_c1[row];
    float c2 = g_c2[row] / g_L[row];
    float4 xv = ((const float4*)x)[(size_t)row * 128 + tid];
    float4 o;
    o.x = fmaf(c1, xv.x, c2 * s.x);
    o.y = fmaf(c1, xv.y, c2 * s.y);
    o.z = fmaf(c1, xv.z, c2 * s.z);
    o.w = fmaf(c1, xv.w, c2 * s.w);
    ((float4*)out)[(size_t)row * 128 + tid] = o;
}

// ---------------------------------------------------------------------------
extern "C" void kernel_launch(void* const* d_in, const int* in_sizes, int n_in,
                              void* d_out, int out_size)
{
    const float* x = (const float*)d_in[0];   // x_t (1024,512)
    const float* t = (const float*)d_in[1];   // t (1024,)
    const float* y = (const float*)d_in[2];   // dataset (100000,512)
    float* out = (float*)d_out;

    static int smem_set = 0;
    if (!smem_set) {
        cudaFuncSetAttribute(qk_kernel,
            cudaFuncAttributeMaxDynamicSharedMemorySize, 2*BK*AST*4 * 2);
        cudaFuncSetAttribute(pv_kernel,
            cudaFuncAttributeMaxDynamicSharedMemorySize, (2*BK*AST + 2*BK*BST3) * 4);
        smem_set = 1;
    }

    prep_kernel<<<12565, 256>>>(x, t, y);
    qk_kernel<<<dim3(NT_M, NT_N), 256, 2*BK*AST*4 * 2>>>(y);
    rowmax_kernel<<<B_SZ, 256>>>();
    pexp_kernel<<<B_SZ, 256>>>();
    pv_kernel<<<dim3(32, NSPL3), 256, (2*BK*AST + 2*BK*BST3) * 4>>>(y);
    combine_kernel<<<B_SZ, 128>>>(x, out);
}

// round 14
// speedup vs baseline: 3.9904x; 2.4392x over previous
#include <cuda_runtime.h>
#include <cuda_fp16.h>
#include <math.h>
#include <stdint.h>

// Problem shapes (fixed)
#define B_SZ 1024
#define N_SZ 100000
#define D_SZ 512
#define NPAD 100096              // 782*128
#define D4   (D_SZ/4)

#define QK_CHUNKS 16             // K=512 / 32
#define PV_SPLITS 8
#define PV_KSPL   (NPAD/PV_SPLITS)     // 12512
#define PV_CHUNKS (PV_KSPL/32)         // 391

#define SMEM_MMA 65536           // 2 stages * 4 tiles * 8KB

// ---------------- scratch (zero-initialized static device globals) ---------
__device__ __half g_xh[B_SZ * D_SZ], g_xl[B_SZ * D_SZ];     // al-scaled x split
__device__ __half g_yh[(size_t)NPAD * D_SZ], g_yl[(size_t)NPAD * D_SZ];   // y [n][d]
__device__ __half g_yth[(size_t)D_SZ * NPAD], g_ytl[(size_t)D_SZ * NPAD]; // y^T [d][n]
__device__ __half g_ph[(size_t)B_SZ * NPAD], g_pl[(size_t)B_SZ * NPAD];   // P split
__device__ float g_be[B_SZ], g_c1[B_SZ], g_c2[B_SZ];
__device__ float g_dsn[NPAD];                                // pad stays 0
__device__ float g_logit[(size_t)B_SZ * NPAD];
__device__ float g_m[B_SZ], g_L[B_SZ];
__device__ float g_pv[(size_t)PV_SPLITS * B_SZ * D_SZ];

// ---------------- helpers ---------------------------------------------------
__device__ __forceinline__ void cp16(unsigned dst, const void* src) {
    asm volatile("cp.async.cg.shared.global [%0], [%1], 16;" :: "r"(dst), "l"(src));
}
#define CP_COMMIT() asm volatile("cp.async.commit_group;")
#define CP_WAIT_1() asm volatile("cp.async.wait_group 1;" ::: "memory")
#define CP_WAIT_0() asm volatile("cp.async.wait_group 0;" ::: "memory")

#define LDSM_X4(r, a) \
    asm volatile("ldmatrix.sync.aligned.m8n8.x4.shared.b16 {%0,%1,%2,%3},[%4];" \
        : "=r"((r)[0]), "=r"((r)[1]), "=r"((r)[2]), "=r"((r)[3]) : "r"(a))
#define MMA16816(c, A, b0, b1) \
    asm volatile("mma.sync.aligned.m16n8k16.row.col.f32.f16.f16.f32 " \
        "{%0,%1,%2,%3},{%4,%5,%6,%7},{%8,%9},{%0,%1,%2,%3};" \
        : "+f"((c)[0]), "+f"((c)[1]), "+f"((c)[2]), "+f"((c)[3]) \
        : "r"((A)[0]), "r"((A)[1]), "r"((A)[2]), "r"((A)[3]), "r"(b0), "r"(b1))

// stage one k32 chunk: 4 tiles (Ahi, Alo, Bhi, Blo), each 128 rows x 32 halves,
// XOR-swizzled so ldmatrix phases are bank-conflict-free.
__device__ __forceinline__ void stage_tiles(unsigned sb,
    const __half* __restrict__ Ah, const __half* __restrict__ Al,
    const __half* __restrict__ Bh, const __half* __restrict__ Bl,
    size_t strA, size_t strB, int ar0, int br0, size_t kh, int tid)
{
    #pragma unroll
    for (int q = 0; q < 2; q++) {
        int i = tid + 256 * q;
        int row = i >> 2, c = i & 3;
        unsigned sw = (unsigned)(row * 64 + ((c ^ ((row >> 1) & 3)) << 4));
        size_t ka = kh + c * 8;
        size_t ra = (size_t)(ar0 + row) * strA + ka;
        size_t rb = (size_t)(br0 + row) * strB + ka;
        cp16(sb +         sw, Ah + ra);
        cp16(sb +  8192 + sw, Al + ra);
        cp16(sb + 16384 + sw, Bh + rb);
        cp16(sb + 24576 + sw, Bl + rb);
    }
    CP_COMMIT();
}

// one k32 chunk of fp16x3 mma: warp tile 64(m) x 32(n).
// B fragments use NON-trans ldmatrix: B stored [n][k] row-major IS the
// col-major k x n operand; non-trans gives thread t 2 consecutive k at n=t/4.
__device__ __forceinline__ void compute_chunk(unsigned sb, int wm, int wn,
                                              int lane, float (&acc)[4][4][4])
{
    #pragma unroll
    for (int ks = 0; ks < 2; ks++) {
        uint32_t ah[4][4], al[4][4], bh[2][4], bl[2][4];
        #pragma unroll
        for (int mf = 0; mf < 4; mf++) {
            int row = wm * 64 + mf * 16 + (lane & 15);
            int c16 = ks * 2 + (lane >> 4);
            unsigned off = (unsigned)(row * 64 + ((c16 ^ ((row >> 1) & 3)) << 4));
            LDSM_X4(ah[mf], sb + off);
            LDSM_X4(al[mf], sb + 8192 + off);
        }
        #pragma unroll
        for (int nf2 = 0; nf2 < 2; nf2++) {
            int row = wn * 32 + nf2 * 16 + (lane & 7) + ((lane >> 4) << 3);
            int c16 = ks * 2 + ((lane >> 3) & 1);
            unsigned off = (unsigned)(row * 64 + ((c16 ^ ((row >> 1) & 3)) << 4));
            LDSM_X4(bh[nf2], sb + 16384 + off);
            LDSM_X4(bl[nf2], sb + 24576 + off);
        }
        #pragma unroll
        for (int mf = 0; mf < 4; mf++)
            #pragma unroll
            for (int nf = 0; nf < 4; nf++)
                MMA16816(acc[mf][nf], ah[mf],
                         bh[nf >> 1][(nf & 1) * 2], bh[nf >> 1][(nf & 1) * 2 + 1]);
        #pragma unroll
        for (int mf = 0; mf < 4; mf++)
            #pragma unroll
            for (int nf = 0; nf < 4; nf++)
                MMA16816(acc[mf][nf], al[mf],
                         bh[nf >> 1][(nf & 1) * 2], bh[nf >> 1][(nf & 1) * 2 + 1]);
        #pragma unroll
        for (int mf = 0; mf < 4; mf++)
            #pragma unroll
            for (int nf = 0; nf < 4; nf++)
                MMA16816(acc[mf][nf], ah[mf],
                         bl[nf >> 1][(nf & 1) * 2], bl[nf >> 1][(nf & 1) * 2 + 1]);
    }
}

// ---------------------------------------------------------------------------
// K0 prep: dsn (blocks 0..12499); coeffs (12500); x' = (a/b^2)x fp16 split
// ---------------------------------------------------------------------------
__global__ void prep_kernel(const float* __restrict__ x,
                            const float* __restrict__ t,
                            const float* __restrict__ y)
{
    int bid = blockIdx.x, tid = threadIdx.x;
    if (bid < 12500) {
        int warp = tid >> 5, lane = tid & 31;
        int n = bid * 8 + warp;
        const float4* y4 = (const float4*)y;
        float s = 0.f;
        #pragma unroll
        for (int k = 0; k < 4; k++) {
            float4 v = y4[(size_t)n * D4 + lane + 32 * k];
            s = fmaf(v.x, v.x, fmaf(v.y, v.y, fmaf(v.z, v.z, fmaf(v.w, v.w, s))));
        }
        #pragma unroll
        for (int off = 16; off > 0; off >>= 1)
            s += __shfl_xor_sync(0xffffffffu, s, off);
        if (lane == 0) g_dsn[n] = s;
    } else if (bid == 12500) {
        #pragma unroll
        for (int q = 0; q < 4; q++) {
            int r = tid + 256 * q;
            float a = t[r], b = 1.f - a;
            g_be[r] = a * a / (2.f * b * b);
            g_c1[r] = -1.f / b;
            g_c2[r] = 1.f + a / b;
        }
    } else {
        int base = (bid - 12501) * 2048;
        const float4* x4 = (const float4*)x;
        #pragma unroll
        for (int q = 0; q < 8; q++) {
            int i = base + tid + 256 * q;
            int row = i >> 7;
            float tv = t[row], b = 1.f - tv;
            float al = tv / (b * b);
            float4 v = x4[i];
            v.x *= al; v.y *= al; v.z *= al; v.w *= al;
            __half hx = __float2half_rn(v.x), hy = __float2half_rn(v.y);
            __half hz = __float2half_rn(v.z), hw = __float2half_rn(v.w);
            __half lx = __float2half_rn(v.x - __half2float(hx));
            __half ly = __float2half_rn(v.y - __half2float(hy));
            __half lz = __float2half_rn(v.z - __half2float(hz));
            __half lw = __float2half_rn(v.w - __half2float(hw));
            size_t a2 = (size_t)i * 2;   // half2 index
            ((__half2*)g_xh)[a2]     = __halves2half2(hx, hy);
            ((__half2*)g_xh)[a2 + 1] = __halves2half2(hz, hw);
            ((__half2*)g_xl)[a2]     = __halves2half2(lx, ly);
            ((__half2*)g_xl)[a2 + 1] = __halves2half2(lz, lw);
        }
    }
}

// ---------------------------------------------------------------------------
// K0b: y fp16 split in [n][d] AND transposed [d][n] (pad regions stay 0)
// grid (3125, 4): tile = 32 n-rows x 128 d-cols
// ---------------------------------------------------------------------------
__global__ void ysplit_kernel(const float* __restrict__ y)
{
    __shared__ float tile[32][129];
    int tid = threadIdx.x;
    int n0 = blockIdx.x * 32;
    int d0 = blockIdx.y * 128;

    #pragma unroll
    for (int q = 0; q < 8; q++) {
        int i = tid + 256 * q;           // 2048: (n, d-pair)
        int r = i >> 6, c2 = i & 63;
        float v0 = y[(size_t)(n0 + r) * D_SZ + d0 + 2 * c2];
        float v1 = y[(size_t)(n0 + r) * D_SZ + d0 + 2 * c2 + 1];
        tile[r][2 * c2] = v0; tile[r][2 * c2 + 1] = v1;
        __half h0 = __float2half_rn(v0), h1 = __float2half_rn(v1);
        __half l0 = __float2half_rn(v0 - __half2float(h0));
        __half l1 = __float2half_rn(v1 - __half2float(h1));
        size_t a = (size_t)(n0 + r) * D_SZ + d0 + 2 * c2;
        ((__half2*)g_yh)[a >> 1] = __halves2half2(h0, h1);
        ((__half2*)g_yl)[a >> 1] = __halves2half2(l0, l1);
    }
    __syncthreads();
    #pragma unroll
    for (int q = 0; q < 8; q++) {
        int i = tid + 256 * q;           // 2048: (d, n-pair)
        int d = i >> 4, np = i & 15;
        float v0 = tile[2 * np][d], v1 = tile[2 * np + 1][d];
        __half h0 = __float2half_rn(v0), h1 = __float2half_rn(v1);
        __half l0 = __float2half_rn(v0 - __half2float(h0));
        __half l1 = __float2half_rn(v1 - __half2float(h1));
        size_t a = (size_t)(d0 + d) * NPAD + n0 + 2 * np;
        ((__half2*)g_yth)[a >> 1] = __halves2half2(h0, h1);
        ((__half2*)g_ytl)[a >> 1] = __halves2half2(l0, l1);
    }
}

// ---------------------------------------------------------------------------
// K1: QK GEMM (fp16x3 HMMA). C[q][k] = x'_q . y_k ; lg = C - be[q]*dsn[k]
// ---------------------------------------------------------------------------
__global__ __launch_bounds__(256) void qk_mma_kernel()
{
    extern __shared__ char smem_raw[];
    const unsigned sm_u = (unsigned)__cvta_generic_to_shared(smem_raw);
    const int tid = threadIdx.x, lane = tid & 31, warp = tid >> 5;
    const int wm = warp >> 2, wn = warp & 3;
    const int m0 = blockIdx.x * 128;     // queries
    const int n0 = blockIdx.y * 128;     // keys

    float acc[4][4][4];
    #pragma unroll
    for (int a = 0; a < 4; a++)
        #pragma unroll
        for (int b = 0; b < 4; b++)
            #pragma unroll
            for (int c = 0; c < 4; c++) acc[a][b][c] = 0.f;

    stage_tiles(sm_u,         g_xh, g_xl, g_yh, g_yl, D_SZ, D_SZ, m0, n0, 0,  tid);
    stage_tiles(sm_u + 32768, g_xh, g_xl, g_yh, g_yl, D_SZ, D_SZ, m0, n0, 32, tid);

    for (int c = 0; c < QK_CHUNKS; c++) {
        unsigned sb = sm_u + (unsigned)(c & 1) * 32768;
        if (c + 1 < QK_CHUNKS) { CP_WAIT_1(); } else { CP_WAIT_0(); }
        __syncthreads();
        compute_chunk(sb, wm, wn, lane, acc);
        __syncthreads();
        if (c + 2 < QK_CHUNKS)
            stage_tiles(sb, g_xh, g_xl, g_yh, g_yl, D_SZ, D_SZ, m0, n0,
                        (size_t)(c + 2) * 32, tid);
    }

    int mg = m0 + wm * 64, ng = n0 + wn * 32;
    #pragma unroll
    for (int mf = 0; mf < 4; mf++) {
        int r1 = mg + mf * 16 + (lane >> 2);
        int r2 = r1 + 8;
        float be1 = g_be[r1], be2 = g_be[r2];
        #pragma unroll
        for (int nf = 0; nf < 4; nf++) {
            int col = ng + nf * 8 + (lane & 3) * 2;
            float d0 = g_dsn[col], d1 = g_dsn[col + 1];
            float2 o1 = make_float2(fmaf(-be1, d0, acc[mf][nf][0]),
                                    fmaf(-be1, d1, acc[mf][nf][1]));
            float2 o2 = make_float2(fmaf(-be2, d0, acc[mf][nf][2]),
                                    fmaf(-be2, d1, acc[mf][nf][3]));
            *(float2*)&g_logit[(size_t)r1 * NPAD + col] = o1;
            *(float2*)&g_logit[(size_t)r2 * NPAD + col] = o2;
        }
    }
}

// ---------------------------------------------------------------------------
// K2a: row max (n < 100000)
// ---------------------------------------------------------------------------
__global__ void rowmax_kernel()
{
    int row = blockIdx.x, tid = threadIdx.x;
    const float4* rp = (const float4*)(g_logit + (size_t)row * NPAD);
    float m = -1e30f;
    for (int c = tid; c < N_SZ / 4; c += 256) {
        float4 v = rp[c];
        m = fmaxf(m, fmaxf(fmaxf(v.x, v.y), fmaxf(v.z, v.w)));
    }
    #pragma unroll
    for (int off = 16; off > 0; off >>= 1)
        m = fmaxf(m, __shfl_xor_sync(0xffffffffu, m, off));
    __shared__ float red[8];
    if ((tid & 31) == 0) red[tid >> 5] = m;
    __syncthreads();
    if (tid == 0) {
        float mm = red[0];
        #pragma unroll
        for (int w = 1; w < 8; w++) mm = fmaxf(mm, red[w]);
        g_m[row] = mm;
    }
}

// ---------------------------------------------------------------------------
// K2b: P = exp(lg - m) split to fp16 hi/lo; L = sum(P). Pad cols stay 0.
// ---------------------------------------------------------------------------
__global__ void pexp_kernel()
{
    int row = blockIdx.x, tid = threadIdx.x;
    const float4* rp = (const float4*)(g_logit + (size_t)row * NPAD);
    __half2* ph2 = (__half2*)(g_ph + (size_t)row * NPAD);
    __half2* pl2 = (__half2*)(g_pl + (size_t)row * NPAD);
    float mr = g_m[row];
    float l = 0.f;
    for (int c = tid; c < N_SZ / 4; c += 256) {
        float4 v = rp[c];
        v.x = __expf(v.x - mr); v.y = __expf(v.y - mr);
        v.z = __expf(v.z - mr); v.w = __expf(v.w - mr);
        l += (v.x + v.y) + (v.z + v.w);
        __half hx = __float2half_rn(v.x), hy = __float2half_rn(v.y);
        __half hz = __float2half_rn(v.z), hw = __float2half_rn(v.w);
        __half lx = __float2half_rn(v.x - __half2float(hx));
        __half ly = __float2half_rn(v.y - __half2float(hy));
        __half lz = __float2half_rn(v.z - __half2float(hz));
        __half lw = __float2half_rn(v.w - __half2float(hw));
        ph2[c * 2]     = __halves2half2(hx, hy);
        ph2[c * 2 + 1] = __halves2half2(hz, hw);
        pl2[c * 2]     = __halves2half2(lx, ly);
        pl2[c * 2 + 1] = __halves2half2(lz, lw);
    }
    #pragma unroll
    for (int off = 16; off > 0; off >>= 1)
        l += __shfl_xor_sync(0xffffffffu, l, off);
    __shared__ float red[8];
    if ((tid & 31) == 0) red[tid >> 5] = l;
    __syncthreads();
    if (tid == 0) {
        float s = red[0];
        #pragma unroll
        for (int w = 1; w < 8; w++) s += red[w];
        g_L[row] = s;
    }
}

// ---------------------------------------------------------------------------
// K3: PV GEMM (fp16x3 HMMA), split-K over 8 splits of 12512 keys.
// C[q][d] = sum_k P[q][k] * yT[d][k] -> g_pv[split]
// ---------------------------------------------------------------------------
__global__ __launch_bounds__(256) void pv_mma_kernel()
{
    extern __shared__ char smem_raw[];
    const unsigned sm_u = (unsigned)__cvta_generic_to_shared(smem_raw);
    const int tid = threadIdx.x, lane = tid & 31, warp = tid >> 5;
    const int wm = warp >> 2, wn = warp & 3;
    const int m0 = (blockIdx.x >> 2) * 128;   // queries
    const int n0 = (blockIdx.x & 3) * 128;    // d dims
    const int split = blockIdx.y;
    const size_t kh0 = (size_t)split * PV_KSPL;

    float acc[4][4][4];
    #pragma unroll
    for (int a = 0; a < 4; a++)
        #pragma unroll
        for (int b = 0; b < 4; b++)
            #pragma unroll
            for (int c = 0; c < 4; c++) acc[a][b][c] = 0.f;

    stage_tiles(sm_u,         g_ph, g_pl, g_yth, g_ytl, NPAD, NPAD, m0, n0, kh0,      tid);
    stage_tiles(sm_u + 32768, g_ph, g_pl, g_yth, g_ytl, NPAD, NPAD, m0, n0, kh0 + 32, tid);

    for (int c = 0; c < PV_CHUNKS; c++) {
        unsigned sb = sm_u + (unsigned)(c & 1) * 32768;
        if (c + 1 < PV_CHUNKS) { CP_WAIT_1(); } else { CP_WAIT_0(); }
        __syncthreads();
        compute_chunk(sb, wm, wn, lane, acc);
        __syncthreads();
        if (c + 2 < PV_CHUNKS)
            stage_tiles(sb, g_ph, g_pl, g_yth, g_ytl, NPAD, NPAD, m0, n0,
                        kh0 + (size_t)(c + 2) * 32, tid);
    }

    int mg = m0 + wm * 64, ng = n0 + wn * 32;
    #pragma unroll
    for (int mf = 0; mf < 4; mf++) {
        int r1 = mg + mf * 16 + (lane >> 2);
        int r2 = r1 + 8;
        #pragma unroll
        for (int nf = 0; nf < 4; nf++) {
            int col = ng + nf * 8 + (lane & 3) * 2;
            size_t b1 = ((size_t)split * B_SZ + r1) * D_SZ + col;
            size_t b2 = ((size_t)split * B_SZ + r2) * D_SZ + col;
            *(float2*)&g_pv[b1] = make_float2(acc[mf][nf][0], acc[mf][nf][1]);
            *(float2*)&g_pv[b2] = make_float2(acc[mf][nf][2], acc[mf][nf][3]);
        }
    }
}

// ---------------------------------------------------------------------------
// K4: combine splits + final affine. v = c1*x + (c2/L) * sum_s pv[s]
// ---------------------------------------------------------------------------
__global__ void combine_kernel(const float* __restrict__ x,
                               float* __restrict__ out)
{
    int row = blockIdx.x, tid = threadIdx.x;   // 128 threads, one float4 each
    const float4* pv4 = (const float4*)g_pv;
    float4 s = make_float4(0.f, 0.f, 0.f, 0.f);
    #pragma unroll
    for (int sp = 0; sp < PV_SPLITS; sp++) {
        float4 v = pv4[((size_t)sp * B_SZ + row) * D4 + tid];
        s.x += v.x; s.y += v.y; s.z += v.z; s.w += v.w;
    }
    float c1 = g_c1[row];
    float c2 = g_c2[row] / g_L[row];
    float4 xv = ((const float4*)x)[(size_t)row * D4 + tid];
    float4 o;
    o.x = fmaf(c1, xv.x, c2 * s.x);
    o.y = fmaf(c1, xv.y, c2 * s.y);
    o.z = fmaf(c1, xv.z, c2 * s.z);
    o.w = fmaf(c1, xv.w, c2 * s.w);
    ((float4*)out)[(size_t)row * D4 + tid] = o;
}

// ---------------------------------------------------------------------------
extern "C" void kernel_launch(void* const* d_in, const int* in_sizes, int n_in,
                              void* d_out, int out_size)
{
    const float* x = (const float*)d_in[0];   // x_t (1024,512)
    const float* t = (const float*)d_in[1];   // t (1024,)
    const float* y = (const float*)d_in[2];   // dataset (100000,512)
    float* out = (float*)d_out;

    static int attr_set = 0;
    if (!attr_set) {
        cudaFuncSetAttribute(qk_mma_kernel,
            cudaFuncAttributeMaxDynamicSharedMemorySize, SMEM_MMA);
        cudaFuncSetAttribute(pv_mma_kernel,
            cudaFuncAttributeMaxDynamicSharedMemorySize, SMEM_MMA);
        attr_set = 1;
    }

    prep_kernel<<<12565, 256>>>(x, t, y);
    ysplit_kernel<<<dim3(3125, 4), 256>>>(y);
    qk_mma_kernel<<<dim3(8, 782), 256, SMEM_MMA>>>();
    rowmax_kernel<<<B_SZ, 256>>>();
    pexp_kernel<<<B_SZ, 256>>>();
    pv_mma_kernel<<<dim3(32, PV_SPLITS), 256, SMEM_MMA>>>();
    combine_kernel<<<B_SZ, 128>>>(x, out);
}

// round 15
// speedup vs baseline: 4.2501x; 1.0651x over previous
#include <cuda_runtime.h>
#include <cuda_fp16.h>
#include <math.h>
#include <stdint.h>

// Problem shapes (fixed)
#define B_SZ 1024
#define N_SZ 100000
#define D_SZ 512
#define NPAD 100096              // 782*128
#define NTILE 782
#define D4   (D_SZ/4)

#define QK_CHUNKS 16             // K=512 / 32
#define PV_SPLITS 4
#define PV_KSPL   (NPAD/PV_SPLITS)     // 25024
#define PV_CHUNKS (PV_KSPL/32)         // 782

#define SMEM_MMA 65536           // 2 stages * 32KB

// ---------------- scratch (zero-initialized static device globals) ---------
__device__ __half g_xh[B_SZ * D_SZ], g_xl[B_SZ * D_SZ];     // al-scaled x split
__device__ __half g_yh[(size_t)NPAD * D_SZ], g_yl[(size_t)NPAD * D_SZ];   // y [n][d]
__device__ __half g_yth[(size_t)D_SZ * NPAD], g_ytl[(size_t)D_SZ * NPAD]; // y^T [d][n]
__device__ __half g_ph[(size_t)B_SZ * NPAD];                 // P fp16 (pad 0)
__device__ float g_be[B_SZ], g_c1[B_SZ], g_c2[B_SZ];
__device__ float g_dsn[NPAD];                                // pad stays 0
__device__ float g_logit[(size_t)B_SZ * NPAD];
__device__ float g_pm[(size_t)B_SZ * NTILE];                 // per-tile row maxes
__device__ float g_m[B_SZ], g_L[B_SZ];
__device__ float g_pv[(size_t)PV_SPLITS * B_SZ * D_SZ];

// ---------------- helpers ---------------------------------------------------
__device__ __forceinline__ void cp16(unsigned dst, const void* src) {
    asm volatile("cp.async.cg.shared.global [%0], [%1], 16;" :: "r"(dst), "l"(src));
}
#define CP_COMMIT() asm volatile("cp.async.commit_group;")
#define CP_WAIT_1() asm volatile("cp.async.wait_group 1;" ::: "memory")
#define CP_WAIT_0() asm volatile("cp.async.wait_group 0;" ::: "memory")

#define LDSM_X4(r, a) \
    asm volatile("ldmatrix.sync.aligned.m8n8.x4.shared.b16 {%0,%1,%2,%3},[%4];" \
        : "=r"((r)[0]), "=r"((r)[1]), "=r"((r)[2]), "=r"((r)[3]) : "r"(a))
#define MMA16816(c, A, b0, b1) \
    asm volatile("mma.sync.aligned.m16n8k16.row.col.f32.f16.f16.f32 " \
        "{%0,%1,%2,%3},{%4,%5,%6,%7},{%8,%9},{%0,%1,%2,%3};" \
        : "+f"((c)[0]), "+f"((c)[1]), "+f"((c)[2]), "+f"((c)[3]) \
        : "r"((A)[0]), "r"((A)[1]), "r"((A)[2]), "r"((A)[3]), "r"(b0), "r"(b1))

// QK staging: 4 tiles (Ahi, Alo, Bhi, Blo), each 128 rows x 32 halves, swizzled
__device__ __forceinline__ void stage_tiles4(unsigned sb,
    const __half* __restrict__ Ah, const __half* __restrict__ Al,
    const __half* __restrict__ Bh, const __half* __restrict__ Bl,
    size_t strA, size_t strB, int ar0, int br0, size_t kh, int tid)
{
    #pragma unroll
    for (int q = 0; q < 2; q++) {
        int i = tid + 256 * q;
        int row = i >> 2, c = i & 3;
        unsigned sw = (unsigned)(row * 64 + ((c ^ ((row >> 1) & 3)) << 4));
        size_t ka = kh + c * 8;
        size_t ra = (size_t)(ar0 + row) * strA + ka;
        size_t rb = (size_t)(br0 + row) * strB + ka;
        cp16(sb +         sw, Ah + ra);
        cp16(sb +  8192 + sw, Al + ra);
        cp16(sb + 16384 + sw, Bh + rb);
        cp16(sb + 24576 + sw, Bl + rb);
    }
    CP_COMMIT();
}

// PV staging: 3 tiles (Ahi=P, Bhi, Blo)
__device__ __forceinline__ void stage_tiles3(unsigned sb,
    const __half* __restrict__ Ah,
    const __half* __restrict__ Bh, const __half* __restrict__ Bl,
    size_t strA, size_t strB, int ar0, int br0, size_t kh, int tid)
{
    #pragma unroll
    for (int q = 0; q < 2; q++) {
        int i = tid + 256 * q;
        int row = i >> 2, c = i & 3;
        unsigned sw = (unsigned)(row * 64 + ((c ^ ((row >> 1) & 3)) << 4));
        size_t ka = kh + c * 8;
        size_t ra = (size_t)(ar0 + row) * strA + ka;
        size_t rb = (size_t)(br0 + row) * strB + ka;
        cp16(sb +         sw, Ah + ra);
        cp16(sb +  8192 + sw, Bh + rb);
        cp16(sb + 16384 + sw, Bl + rb);
    }
    CP_COMMIT();
}

// QK chunk: 3 passes (ah*bh, al*bh, ah*bl); warp tile 64x32
__device__ __forceinline__ void compute_chunk3(unsigned sb, int wm, int wn,
                                               int lane, float (&acc)[4][4][4])
{
    #pragma unroll
    for (int ks = 0; ks < 2; ks++) {
        uint32_t ah[4][4], al[4][4], bh[2][4], bl[2][4];
        #pragma unroll
        for (int mf = 0; mf < 4; mf++) {
            int row = wm * 64 + mf * 16 + (lane & 15);
            int c16 = ks * 2 + (lane >> 4);
            unsigned off = (unsigned)(row * 64 + ((c16 ^ ((row >> 1) & 3)) << 4));
            LDSM_X4(ah[mf], sb + off);
            LDSM_X4(al[mf], sb + 8192 + off);
        }
        #pragma unroll
        for (int nf2 = 0; nf2 < 2; nf2++) {
            int row = wn * 32 + nf2 * 16 + (lane & 7) + ((lane >> 4) << 3);
            int c16 = ks * 2 + ((lane >> 3) & 1);
            unsigned off = (unsigned)(row * 64 + ((c16 ^ ((row >> 1) & 3)) << 4));
            LDSM_X4(bh[nf2], sb + 16384 + off);
            LDSM_X4(bl[nf2], sb + 24576 + off);
        }
        #pragma unroll
        for (int mf = 0; mf < 4; mf++)
            #pragma unroll
            for (int nf = 0; nf < 4; nf++)
                MMA16816(acc[mf][nf], ah[mf],
                         bh[nf >> 1][(nf & 1) * 2], bh[nf >> 1][(nf & 1) * 2 + 1]);
        #pragma unroll
        for (int mf = 0; mf < 4; mf++)
            #pragma unroll
            for (int nf = 0; nf < 4; nf++)
                MMA16816(acc[mf][nf], al[mf],
                         bh[nf >> 1][(nf & 1) * 2], bh[nf >> 1][(nf & 1) * 2 + 1]);
        #pragma unroll
        for (int mf = 0; mf < 4; mf++)
            #pragma unroll
            for (int nf = 0; nf < 4; nf++)
                MMA16816(acc[mf][nf], ah[mf],
                         bl[nf >> 1][(nf & 1) * 2], bl[nf >> 1][(nf & 1) * 2 + 1]);
    }
}

// PV chunk: 2 passes (ah*bh, ah*bl)
__device__ __forceinline__ void compute_chunk2(unsigned sb, int wm, int wn,
                                               int lane, float (&acc)[4][4][4])
{
    #pragma unroll
    for (int ks = 0; ks < 2; ks++) {
        uint32_t ah[4][4], bh[2][4], bl[2][4];
        #pragma unroll
        for (int mf = 0; mf < 4; mf++) {
            int row = wm * 64 + mf * 16 + (lane & 15);
            int c16 = ks * 2 + (lane >> 4);
            unsigned off = (unsigned)(row * 64 + ((c16 ^ ((row >> 1) & 3)) << 4));
            LDSM_X4(ah[mf], sb + off);
        }
        #pragma unroll
        for (int nf2 = 0; nf2 < 2; nf2++) {
            int row = wn * 32 + nf2 * 16 + (lane & 7) + ((lane >> 4) << 3);
            int c16 = ks * 2 + ((lane >> 3) & 1);
            unsigned off = (unsigned)(row * 64 + ((c16 ^ ((row >> 1) & 3)) << 4));
            LDSM_X4(bh[nf2], sb + 8192 + off);
            LDSM_X4(bl[nf2], sb + 16384 + off);
        }
        #pragma unroll
        for (int mf = 0; mf < 4; mf++)
            #pragma unroll
            for (int nf = 0; nf < 4; nf++)
                MMA16816(acc[mf][nf], ah[mf],
                         bh[nf >> 1][(nf & 1) * 2], bh[nf >> 1][(nf & 1) * 2 + 1]);
        #pragma unroll
        for (int mf = 0; mf < 4; mf++)
            #pragma unroll
            for (int nf = 0; nf < 4; nf++)
                MMA16816(acc[mf][nf], ah[mf],
                         bl[nf >> 1][(nf & 1) * 2], bl[nf >> 1][(nf & 1) * 2 + 1]);
    }
}

// ---------------------------------------------------------------------------
// K0 prep: dsn (blocks 0..12499); coeffs (12500); x' = (a/b^2)x fp16 split
// ---------------------------------------------------------------------------
__global__ void prep_kernel(const float* __restrict__ x,
                            const float* __restrict__ t,
                            const float* __restrict__ y)
{
    int bid = blockIdx.x, tid = threadIdx.x;
    if (bid < 12500) {
        int warp = tid >> 5, lane = tid & 31;
        int n = bid * 8 + warp;
        const float4* y4 = (const float4*)y;
        float s = 0.f;
        #pragma unroll
        for (int k = 0; k < 4; k++) {
            float4 v = y4[(size_t)n * D4 + lane + 32 * k];
            s = fmaf(v.x, v.x, fmaf(v.y, v.y, fmaf(v.z, v.z, fmaf(v.w, v.w, s))));
        }
        #pragma unroll
        for (int off = 16; off > 0; off >>= 1)
            s += __shfl_xor_sync(0xffffffffu, s, off);
        if (lane == 0) g_dsn[n] = s;
    } else if (bid == 12500) {
        #pragma unroll
        for (int q = 0; q < 4; q++) {
            int r = tid + 256 * q;
            float a = t[r], b = 1.f - a;
            g_be[r] = a * a / (2.f * b * b);
            g_c1[r] = -1.f / b;
            g_c2[r] = 1.f + a / b;
        }
    } else {
        int base = (bid - 12501) * 2048;
        const float4* x4 = (const float4*)x;
        #pragma unroll
        for (int q = 0; q < 8; q++) {
            int i = base + tid + 256 * q;
            int row = i >> 7;
            float tv = t[row], b = 1.f - tv;
            float al = tv / (b * b);
            float4 v = x4[i];
            v.x *= al; v.y *= al; v.z *= al; v.w *= al;
            __half hx = __float2half_rn(v.x), hy = __float2half_rn(v.y);
            __half hz = __float2half_rn(v.z), hw = __float2half_rn(v.w);
            __half lx = __float2half_rn(v.x - __half2float(hx));
            __half ly = __float2half_rn(v.y - __half2float(hy));
            __half lz = __float2half_rn(v.z - __half2float(hz));
            __half lw = __float2half_rn(v.w - __half2float(hw));
            size_t a2 = (size_t)i * 2;   // half2 index
            ((__half2*)g_xh)[a2]     = __halves2half2(hx, hy);
            ((__half2*)g_xh)[a2 + 1] = __halves2half2(hz, hw);
            ((__half2*)g_xl)[a2]     = __halves2half2(lx, ly);
            ((__half2*)g_xl)[a2 + 1] = __halves2half2(lz, lw);
        }
    }
}

// ---------------------------------------------------------------------------
// K0b: y fp16 split in [n][d] AND transposed [d][n] (pad regions stay 0)
// ---------------------------------------------------------------------------
__global__ void ysplit_kernel(const float* __restrict__ y)
{
    __shared__ float tile[32][129];
    int tid = threadIdx.x;
    int n0 = blockIdx.x * 32;
    int d0 = blockIdx.y * 128;

    #pragma unroll
    for (int q = 0; q < 8; q++) {
        int i = tid + 256 * q;           // 2048: (n, d-pair)
        int r = i >> 6, c2 = i & 63;
        float v0 = y[(size_t)(n0 + r) * D_SZ + d0 + 2 * c2];
        float v1 = y[(size_t)(n0 + r) * D_SZ + d0 + 2 * c2 + 1];
        tile[r][2 * c2] = v0; tile[r][2 * c2 + 1] = v1;
        __half h0 = __float2half_rn(v0), h1 = __float2half_rn(v1);
        __half l0 = __float2half_rn(v0 - __half2float(h0));
        __half l1 = __float2half_rn(v1 - __half2float(h1));
        size_t a = (size_t)(n0 + r) * D_SZ + d0 + 2 * c2;
        ((__half2*)g_yh)[a >> 1] = __halves2half2(h0, h1);
        ((__half2*)g_yl)[a >> 1] = __halves2half2(l0, l1);
    }
    __syncthreads();
    #pragma unroll
    for (int q = 0; q < 8; q++) {
        int i = tid + 256 * q;           // 2048: (d, n-pair)
        int d = i >> 4, np = i & 15;
        float v0 = tile[2 * np][d], v1 = tile[2 * np + 1][d];
        __half h0 = __float2half_rn(v0), h1 = __float2half_rn(v1);
        __half l0 = __float2half_rn(v0 - __half2float(h0));
        __half l1 = __float2half_rn(v1 - __half2float(h1));
        size_t a = (size_t)(d0 + d) * NPAD + n0 + 2 * np;
        ((__half2*)g_yth)[a >> 1] = __halves2half2(h0, h1);
        ((__half2*)g_ytl)[a >> 1] = __halves2half2(l0, l1);
    }
}

// ---------------------------------------------------------------------------
// K1: QK GEMM (fp16x3 HMMA). lg = C - be[q]*dsn[k]; fused per-tile row max
// ---------------------------------------------------------------------------
__global__ __launch_bounds__(256) void qk_mma_kernel()
{
    extern __shared__ char smem_raw[];
    __shared__ float smax[4][128];
    const unsigned sm_u = (unsigned)__cvta_generic_to_shared(smem_raw);
    const int tid = threadIdx.x, lane = tid & 31, warp = tid >> 5;
    const int wm = warp >> 2, wn = warp & 3;
    const int m0 = blockIdx.x * 128;     // queries
    const int n0 = blockIdx.y * 128;     // keys

    float acc[4][4][4];
    #pragma unroll
    for (int a = 0; a < 4; a++)
        #pragma unroll
        for (int b = 0; b < 4; b++)
            #pragma unroll
            for (int c = 0; c < 4; c++) acc[a][b][c] = 0.f;

    stage_tiles4(sm_u,         g_xh, g_xl, g_yh, g_yl, D_SZ, D_SZ, m0, n0, 0,  tid);
    stage_tiles4(sm_u + 32768, g_xh, g_xl, g_yh, g_yl, D_SZ, D_SZ, m0, n0, 32, tid);

    for (int c = 0; c < QK_CHUNKS; c++) {
        unsigned sb = sm_u + (unsigned)(c & 1) * 32768;
        if (c + 1 < QK_CHUNKS) { CP_WAIT_1(); } else { CP_WAIT_0(); }
        __syncthreads();
        compute_chunk3(sb, wm, wn, lane, acc);
        __syncthreads();
        if (c + 2 < QK_CHUNKS)
            stage_tiles4(sb, g_xh, g_xl, g_yh, g_yl, D_SZ, D_SZ, m0, n0,
                         (size_t)(c + 2) * 32, tid);
    }

    int mg = m0 + wm * 64, ng = n0 + wn * 32;
    #pragma unroll
    for (int mf = 0; mf < 4; mf++) {
        int r1 = mg + mf * 16 + (lane >> 2);
        int r2 = r1 + 8;
        float be1 = g_be[r1], be2 = g_be[r2];
        float mx1 = -1e30f, mx2 = -1e30f;
        #pragma unroll
        for (int nf = 0; nf < 4; nf++) {
            int col = ng + nf * 8 + (lane & 3) * 2;
            float d0 = g_dsn[col], d1 = g_dsn[col + 1];
            float2 o1 = make_float2(fmaf(-be1, d0, acc[mf][nf][0]),
                                    fmaf(-be1, d1, acc[mf][nf][1]));
            float2 o2 = make_float2(fmaf(-be2, d0, acc[mf][nf][2]),
                                    fmaf(-be2, d1, acc[mf][nf][3]));
            *(float2*)&g_logit[(size_t)r1 * NPAD + col] = o1;
            *(float2*)&g_logit[(size_t)r2 * NPAD + col] = o2;
            if (col < N_SZ) {            // mask pad keys out of the max
                mx1 = fmaxf(mx1, fmaxf(o1.x, o1.y));
                mx2 = fmaxf(mx2, fmaxf(o2.x, o2.y));
            }
        }
        // reduce over the 4 lanes sharing each row
        mx1 = fmaxf(mx1, __shfl_xor_sync(0xffffffffu, mx1, 1));
        mx1 = fmaxf(mx1, __shfl_xor_sync(0xffffffffu, mx1, 2));
        mx2 = fmaxf(mx2, __shfl_xor_sync(0xffffffffu, mx2, 1));
        mx2 = fmaxf(mx2, __shfl_xor_sync(0xffffffffu, mx2, 2));
        if ((lane & 3) == 0) {
            smax[wn][wm * 64 + mf * 16 + (lane >> 2)]     = mx1;
            smax[wn][wm * 64 + mf * 16 + (lane >> 2) + 8] = mx2;
        }
    }
    __syncthreads();
    if (tid < 128) {
        float m = fmaxf(fmaxf(smax[0][tid], smax[1][tid]),
                        fmaxf(smax[2][tid], smax[3][tid]));
        g_pm[(size_t)(m0 + tid) * NTILE + blockIdx.y] = m;
    }
}

// ---------------------------------------------------------------------------
// K2a: row max over per-tile partial maxes (782 per row)
// ---------------------------------------------------------------------------
__global__ void rowmax_kernel()
{
    int row = blockIdx.x, tid = threadIdx.x;
    const float* rp = g_pm + (size_t)row * NTILE;
    float m = -1e30f;
    for (int c = tid; c < NTILE; c += 256) m = fmaxf(m, rp[c]);
    #pragma unroll
    for (int off = 16; off > 0; off >>= 1)
        m = fmaxf(m, __shfl_xor_sync(0xffffffffu, m, off));
    __shared__ float red[8];
    if ((tid & 31) == 0) red[tid >> 5] = m;
    __syncthreads();
    if (tid == 0) {
        float mm = red[0];
        #pragma unroll
        for (int w = 1; w < 8; w++) mm = fmaxf(mm, red[w]);
        g_m[row] = mm;
    }
}

// ---------------------------------------------------------------------------
// K2b: P = exp(lg - m) -> fp16 (hi only); L = sum(P). Pad cols stay 0.
// ---------------------------------------------------------------------------
__global__ void pexp_kernel()
{
    int row = blockIdx.x, tid = threadIdx.x;
    const float4* rp = (const float4*)(g_logit + (size_t)row * NPAD);
    __half2* ph2 = (__half2*)(g_ph + (size_t)row * NPAD);
    float mr = g_m[row];
    float l = 0.f;
    for (int c = tid; c < N_SZ / 4; c += 256) {
        float4 v = rp[c];
        v.x = __expf(v.x - mr); v.y = __expf(v.y - mr);
        v.z = __expf(v.z - mr); v.w = __expf(v.w - mr);
        l += (v.x + v.y) + (v.z + v.w);
        ph2[c * 2]     = __halves2half2(__float2half_rn(v.x), __float2half_rn(v.y));
        ph2[c * 2 + 1] = __halves2half2(__float2half_rn(v.z), __float2half_rn(v.w));
    }
    #pragma unroll
    for (int off = 16; off > 0; off >>= 1)
        l += __shfl_xor_sync(0xffffffffu, l, off);
    __shared__ float red[8];
    if ((tid & 31) == 0) red[tid >> 5] = l;
    __syncthreads();
    if (tid == 0) {
        float s = red[0];
        #pragma unroll
        for (int w = 1; w < 8; w++) s += red[w];
        g_L[row] = s;
    }
}

// ---------------------------------------------------------------------------
// K3: PV GEMM (fp16x2 HMMA), split-K over 4 splits of 25024 keys.
// C[q][d] = sum_k P[q][k] * yT[d][k] -> g_pv[split]
// ---------------------------------------------------------------------------
__global__ __launch_bounds__(256) void pv_mma_kernel()
{
    extern __shared__ char smem_raw[];
    const unsigned sm_u = (unsigned)__cvta_generic_to_shared(smem_raw);
    const int tid = threadIdx.x, lane = tid & 31, warp = tid >> 5;
    const int wm = warp >> 2, wn = warp & 3;
    const int m0 = (blockIdx.x >> 2) * 128;   // queries
    const int n0 = (blockIdx.x & 3) * 128;    // d dims
    const int split = blockIdx.y;
    const size_t kh0 = (size_t)split * PV_KSPL;

    float acc[4][4][4];
    #pragma unroll
    for (int a = 0; a < 4; a++)
        #pragma unroll
        for (int b = 0; b < 4; b++)
            #pragma unroll
            for (int c = 0; c < 4; c++) acc[a][b][c] = 0.f;

    stage_tiles3(sm_u,         g_ph, g_yth, g_ytl, NPAD, NPAD, m0, n0, kh0,      tid);
    stage_tiles3(sm_u + 32768, g_ph, g_yth, g_ytl, NPAD, NPAD, m0, n0, kh0 + 32, tid);

    for (int c = 0; c < PV_CHUNKS; c++) {
        unsigned sb = sm_u + (unsigned)(c & 1) * 32768;
        if (c + 1 < PV_CHUNKS) { CP_WAIT_1(); } else { CP_WAIT_0(); }
        __syncthreads();
        compute_chunk2(sb, wm, wn, lane, acc);
        __syncthreads();
        if (c + 2 < PV_CHUNKS)
            stage_tiles3(sb, g_ph, g_yth, g_ytl, NPAD, NPAD, m0, n0,
                         kh0 + (size_t)(c + 2) * 32, tid);
    }

    int mg = m0 + wm * 64, ng = n0 + wn * 32;
    #pragma unroll
    for (int mf = 0; mf < 4; mf++) {
        int r1 = mg + mf * 16 + (lane >> 2);
        int r2 = r1 + 8;
        #pragma unroll
        for (int nf = 0; nf < 4; nf++) {
            int col = ng + nf * 8 + (lane & 3) * 2;
            size_t b1 = ((size_t)split * B_SZ + r1) * D_SZ + col;
            size_t b2 = ((size_t)split * B_SZ + r2) * D_SZ + col;
            *(float2*)&g_pv[b1] = make_float2(acc[mf][nf][0], acc[mf][nf][1]);
            *(float2*)&g_pv[b2] = make_float2(acc[mf][nf][2], acc[mf][nf][3]);
        }
    }
}

// ---------------------------------------------------------------------------
// K4: combine splits + final affine. v = c1*x + (c2/L) * sum_s pv[s]
// ---------------------------------------------------------------------------
__global__ void combine_kernel(const float* __restrict__ x,
                               float* __restrict__ out)
{
    int row = blockIdx.x, tid = threadIdx.x;   // 128 threads, one float4 each
    const float4* pv4 = (const float4*)g_pv;
    float4 s = make_float4(0.f, 0.f, 0.f, 0.f);
    #pragma unroll
    for (int sp = 0; sp < PV_SPLITS; sp++) {
        float4 v = pv4[((size_t)sp * B_SZ + row) * D4 + tid];
        s.x += v.x; s.y += v.y; s.z += v.z; s.w += v.w;
    }
    float c1 = g_c1[row];
    float c2 = g_c2[row] / g_L[row];
    float4 xv = ((const float4*)x)[(size_t)row * D4 + tid];
    float4 o;
    o.x = fmaf(c1, xv.x, c2 * s.x);
    o.y = fmaf(c1, xv.y, c2 * s.y);
    o.z = fmaf(c1, xv.z, c2 * s.z);
    o.w = fmaf(c1, xv.w, c2 * s.w);
    ((float4*)out)[(size_t)row * D4 + tid] = o;
}

// ---------------------------------------------------------------------------
extern "C" void kernel_launch(void* const* d_in, const int* in_sizes, int n_in,
                              void* d_out, int out_size)
{
    const float* x = (const float*)d_in[0];   // x_t (1024,512)
    const float* t = (const float*)d_in[1];   // t (1024,)
    const float* y = (const float*)d_in[2];   // dataset (100000,512)
    float* out = (float*)d_out;

    static int attr_set = 0;
    if (!attr_set) {
        cudaFuncSetAttribute(qk_mma_kernel,
            cudaFuncAttributeMaxDynamicSharedMemorySize, SMEM_MMA);
        cudaFuncSetAttribute(pv_mma_kernel,
            cudaFuncAttributeMaxDynamicSharedMemorySize, SMEM_MMA);
        attr_set = 1;
    }

    prep_kernel<<<12565, 256>>>(x, t, y);
    ysplit_kernel<<<dim3(3125, 4), 256>>>(y);
    qk_mma_kernel<<<dim3(8, NTILE), 256, SMEM_MMA>>>();
    rowmax_kernel<<<B_SZ, 256>>>();
    pexp_kernel<<<B_SZ, 256>>>();
    pv_mma_kernel<<<dim3(32, PV_SPLITS), 256, SMEM_MMA>>>();
    combine_kernel<<<B_SZ, 128>>>(x, out);
}

// round 16
// speedup vs baseline: 5.2120x; 1.2263x over previous
#include <cuda_runtime.h>
#include <cuda_fp16.h>
#include <math.h>
#include <stdint.h>

// Problem shapes (fixed)
#define B_SZ 1024
#define N_SZ 100000
#define D_SZ 512
#define NPAD 100096              // 782*128
#define NTILE 782
#define D4   (D_SZ/4)

#define QK_CHUNKS 16             // K=512 / 32
#define PV_SPLITS 4
#define PV_KSPL   (NPAD/PV_SPLITS)     // 25024
#define PV_CHUNKS (PV_KSPL/64)         // 391 (k64 chunks)

#define SMEM_MMA 65536           // QK: 2 stages*32KB ; PV: 2 stages*32KB

// ---------------- scratch (zero-initialized static device globals) ---------
__device__ __half g_xh[B_SZ * D_SZ], g_xl[B_SZ * D_SZ];     // al-scaled x split
__device__ __half g_yh[(size_t)NPAD * D_SZ], g_yl[(size_t)NPAD * D_SZ];   // y [n][d]
__device__ __half g_yth[(size_t)D_SZ * NPAD];                // y^T hi [d][n]
__device__ __half g_ph[(size_t)B_SZ * NPAD];                 // P fp16 (pad 0)
__device__ float g_be[B_SZ], g_c1[B_SZ], g_c2[B_SZ];
__device__ float g_dsn[NPAD];                                // pad stays 0
__device__ float g_logit[(size_t)B_SZ * NPAD];
__device__ float g_pm[(size_t)B_SZ * NTILE];                 // per-tile row maxes
__device__ float g_L[B_SZ];
__device__ float g_pv[(size_t)PV_SPLITS * B_SZ * D_SZ];

// ---------------- helpers ---------------------------------------------------
__device__ __forceinline__ void cp16(unsigned dst, const void* src) {
    asm volatile("cp.async.cg.shared.global [%0], [%1], 16;" :: "r"(dst), "l"(src));
}
#define CP_COMMIT() asm volatile("cp.async.commit_group;")
#define CP_WAIT_1() asm volatile("cp.async.wait_group 1;" ::: "memory")
#define CP_WAIT_0() asm volatile("cp.async.wait_group 0;" ::: "memory")

#define LDSM_X4(r, a) \
    asm volatile("ldmatrix.sync.aligned.m8n8.x4.shared.b16 {%0,%1,%2,%3},[%4];" \
        : "=r"((r)[0]), "=r"((r)[1]), "=r"((r)[2]), "=r"((r)[3]) : "r"(a))
#define MMA16816(c, A, b0, b1) \
    asm volatile("mma.sync.aligned.m16n8k16.row.col.f32.f16.f16.f32 " \
        "{%0,%1,%2,%3},{%4,%5,%6,%7},{%8,%9},{%0,%1,%2,%3};" \
        : "+f"((c)[0]), "+f"((c)[1]), "+f"((c)[2]), "+f"((c)[3]) \
        : "r"((A)[0]), "r"((A)[1]), "r"((A)[2]), "r"((A)[3]), "r"(b0), "r"(b1))

// ---- QK staging (k32 rows of 64B, swizzle c^((row>>1)&3)) ------------------
__device__ __forceinline__ void stage_tiles4(unsigned sb,
    const __half* __restrict__ Ah, const __half* __restrict__ Al,
    const __half* __restrict__ Bh, const __half* __restrict__ Bl,
    size_t strA, size_t strB, int ar0, int br0, size_t kh, int tid)
{
    #pragma unroll
    for (int q = 0; q < 2; q++) {
        int i = tid + 256 * q;
        int row = i >> 2, c = i & 3;
        unsigned sw = (unsigned)(row * 64 + ((c ^ ((row >> 1) & 3)) << 4));
        size_t ka = kh + c * 8;
        size_t ra = (size_t)(ar0 + row) * strA + ka;
        size_t rb = (size_t)(br0 + row) * strB + ka;
        cp16(sb +         sw, Ah + ra);
        cp16(sb +  8192 + sw, Al + ra);
        cp16(sb + 16384 + sw, Bh + rb);
        cp16(sb + 24576 + sw, Bl + rb);
    }
    CP_COMMIT();
}

// QK chunk: 3 passes (ah*bh, al*bh, ah*bl); warp tile 64x32
__device__ __forceinline__ void compute_chunk3(unsigned sb, int wm, int wn,
                                               int lane, float (&acc)[4][4][4])
{
    #pragma unroll
    for (int ks = 0; ks < 2; ks++) {
        uint32_t ah[4][4], al[4][4], bh[2][4], bl[2][4];
        #pragma unroll
        for (int mf = 0; mf < 4; mf++) {
            int row = wm * 64 + mf * 16 + (lane & 15);
            int c16 = ks * 2 + (lane >> 4);
            unsigned off = (unsigned)(row * 64 + ((c16 ^ ((row >> 1) & 3)) << 4));
            LDSM_X4(ah[mf], sb + off);
            LDSM_X4(al[mf], sb + 8192 + off);
        }
        #pragma unroll
        for (int nf2 = 0; nf2 < 2; nf2++) {
            int row = wn * 32 + nf2 * 16 + (lane & 7) + ((lane >> 4) << 3);
            int c16 = ks * 2 + ((lane >> 3) & 1);
            unsigned off = (unsigned)(row * 64 + ((c16 ^ ((row >> 1) & 3)) << 4));
            LDSM_X4(bh[nf2], sb + 16384 + off);
            LDSM_X4(bl[nf2], sb + 24576 + off);
        }
        #pragma unroll
        for (int mf = 0; mf < 4; mf++)
            #pragma unroll
            for (int nf = 0; nf < 4; nf++)
                MMA16816(acc[mf][nf], ah[mf],
                         bh[nf >> 1][(nf & 1) * 2], bh[nf >> 1][(nf & 1) * 2 + 1]);
        #pragma unroll
        for (int mf = 0; mf < 4; mf++)
            #pragma unroll
            for (int nf = 0; nf < 4; nf++)
                MMA16816(acc[mf][nf], al[mf],
                         bh[nf >> 1][(nf & 1) * 2], bh[nf >> 1][(nf & 1) * 2 + 1]);
        #pragma unroll
        for (int mf = 0; mf < 4; mf++)
            #pragma unroll
            for (int nf = 0; nf < 4; nf++)
                MMA16816(acc[mf][nf], ah[mf],
                         bl[nf >> 1][(nf & 1) * 2], bl[nf >> 1][(nf & 1) * 2 + 1]);
    }
}

// ---- PV staging (k64 rows of 128B, swizzle c^(row&7)) ----------------------
__device__ __forceinline__ void stage_pv(unsigned sb,
    const __half* __restrict__ Ah, const __half* __restrict__ Bh,
    size_t strA, size_t strB, int ar0, int br0, size_t kh, int tid)
{
    #pragma unroll
    for (int q = 0; q < 4; q++) {
        int i = tid + 256 * q;           // 1024 = 128 rows * 8 c16
        int row = i >> 3, c = i & 7;
        unsigned sw = (unsigned)(row * 128 + ((c ^ (row & 7)) << 4));
        size_t ka = kh + c * 8;
        cp16(sb +         sw, Ah + (size_t)(ar0 + row) * strA + ka);
        cp16(sb + 16384 + sw, Bh + (size_t)(br0 + row) * strB + ka);
    }
    CP_COMMIT();
}

// PV chunk (k64, 1 pass): warp tile 64x32
__device__ __forceinline__ void compute_pv(unsigned sb, int wm, int wn,
                                           int lane, float (&acc)[4][4][4])
{
    #pragma unroll
    for (int ks = 0; ks < 4; ks++) {
        uint32_t ah[4][4], bh[2][4];
        #pragma unroll
        for (int mf = 0; mf < 4; mf++) {
            int row = wm * 64 + mf * 16 + (lane & 15);
            int c16 = ks * 2 + (lane >> 4);
            unsigned off = (unsigned)(row * 128 + ((c16 ^ (row & 7)) << 4));
            LDSM_X4(ah[mf], sb + off);
        }
        #pragma unroll
        for (int nf2 = 0; nf2 < 2; nf2++) {
            int row = wn * 32 + nf2 * 16 + (lane & 7) + ((lane >> 4) << 3);
            int c16 = ks * 2 + ((lane >> 3) & 1);
            unsigned off = (unsigned)(row * 128 + ((c16 ^ (row & 7)) << 4));
            LDSM_X4(bh[nf2], sb + 16384 + off);
        }
        #pragma unroll
        for (int mf = 0; mf < 4; mf++)
            #pragma unroll
            for (int nf = 0; nf < 4; nf++)
                MMA16816(acc[mf][nf], ah[mf],
                         bh[nf >> 1][(nf & 1) * 2], bh[nf >> 1][(nf & 1) * 2 + 1]);
    }
}

// ---------------------------------------------------------------------------
// K0 prep: dsn (blocks 0..12499); coeffs (12500); x' = (a/b^2)x fp16 split
// ---------------------------------------------------------------------------
__global__ void prep_kernel(const float* __restrict__ x,
                            const float* __restrict__ t,
                            const float* __restrict__ y)
{
    int bid = blockIdx.x, tid = threadIdx.x;
    if (bid < 12500) {
        int warp = tid >> 5, lane = tid & 31;
        int n = bid * 8 + warp;
        const float4* y4 = (const float4*)y;
        float s = 0.f;
        #pragma unroll
        for (int k = 0; k < 4; k++) {
            float4 v = y4[(size_t)n * D4 + lane + 32 * k];
            s = fmaf(v.x, v.x, fmaf(v.y, v.y, fmaf(v.z, v.z, fmaf(v.w, v.w, s))));
        }
        #pragma unroll
        for (int off = 16; off > 0; off >>= 1)
            s += __shfl_xor_sync(0xffffffffu, s, off);
        if (lane == 0) g_dsn[n] = s;
    } else if (bid == 12500) {
        #pragma unroll
        for (int q = 0; q < 4; q++) {
            int r = tid + 256 * q;
            float a = t[r], b = 1.f - a;
            g_be[r] = a * a / (2.f * b * b);
            g_c1[r] = -1.f / b;
            g_c2[r] = 1.f + a / b;
        }
    } else {
        int base = (bid - 12501) * 2048;
        const float4* x4 = (const float4*)x;
        #pragma unroll
        for (int q = 0; q < 8; q++) {
            int i = base + tid + 256 * q;
            int row = i >> 7;
            float tv = t[row], b = 1.f - tv;
            float al = tv / (b * b);
            float4 v = x4[i];
            v.x *= al; v.y *= al; v.z *= al; v.w *= al;
            __half hx = __float2half_rn(v.x), hy = __float2half_rn(v.y);
            __half hz = __float2half_rn(v.z), hw = __float2half_rn(v.w);
            __half lx = __float2half_rn(v.x - __half2float(hx));
            __half ly = __float2half_rn(v.y - __half2float(hy));
            __half lz = __float2half_rn(v.z - __half2float(hz));
            __half lw = __float2half_rn(v.w - __half2float(hw));
            size_t a2 = (size_t)i * 2;   // half2 index
            ((__half2*)g_xh)[a2]     = __halves2half2(hx, hy);
            ((__half2*)g_xh)[a2 + 1] = __halves2half2(hz, hw);
            ((__half2*)g_xl)[a2]     = __halves2half2(lx, ly);
            ((__half2*)g_xl)[a2 + 1] = __halves2half2(lz, lw);
        }
    }
}

// ---------------------------------------------------------------------------
// K0b: y fp16 split [n][d] (hi+lo) and transposed hi [d][n] (pad stays 0)
// ---------------------------------------------------------------------------
__global__ void ysplit_kernel(const float* __restrict__ y)
{
    __shared__ float tile[32][129];
    int tid = threadIdx.x;
    int n0 = blockIdx.x * 32;
    int d0 = blockIdx.y * 128;

    #pragma unroll
    for (int q = 0; q < 8; q++) {
        int i = tid + 256 * q;           // 2048: (n, d-pair)
        int r = i >> 6, c2 = i & 63;
        float v0 = y[(size_t)(n0 + r) * D_SZ + d0 + 2 * c2];
        float v1 = y[(size_t)(n0 + r) * D_SZ + d0 + 2 * c2 + 1];
        tile[r][2 * c2] = v0; tile[r][2 * c2 + 1] = v1;
        __half h0 = __float2half_rn(v0), h1 = __float2half_rn(v1);
        __half l0 = __float2half_rn(v0 - __half2float(h0));
        __half l1 = __float2half_rn(v1 - __half2float(h1));
        size_t a = (size_t)(n0 + r) * D_SZ + d0 + 2 * c2;
        ((__half2*)g_yh)[a >> 1] = __halves2half2(h0, h1);
        ((__half2*)g_yl)[a >> 1] = __halves2half2(l0, l1);
    }
    __syncthreads();
    #pragma unroll
    for (int q = 0; q < 8; q++) {
        int i = tid + 256 * q;           // 2048: (d, n-pair)
        int d = i >> 4, np = i & 15;
        float v0 = tile[2 * np][d], v1 = tile[2 * np + 1][d];
        __half h0 = __float2half_rn(v0), h1 = __float2half_rn(v1);
        size_t a = (size_t)(d0 + d) * NPAD + n0 + 2 * np;
        ((__half2*)g_yth)[a >> 1] = __halves2half2(h0, h1);
    }
}

// ---------------------------------------------------------------------------
// K1: QK GEMM (fp16x3 HMMA). lg = C - be[q]*dsn[k]; fused per-tile row max
// ---------------------------------------------------------------------------
__global__ __launch_bounds__(256) void qk_mma_kernel()
{
    extern __shared__ char smem_raw[];
    __shared__ float smax[4][128];
    const unsigned sm_u = (unsigned)__cvta_generic_to_shared(smem_raw);
    const int tid = threadIdx.x, lane = tid & 31, warp = tid >> 5;
    const int wm = warp >> 2, wn = warp & 3;
    const int m0 = blockIdx.x * 128;     // queries
    const int n0 = blockIdx.y * 128;     // keys

    float acc[4][4][4];
    #pragma unroll
    for (int a = 0; a < 4; a++)
        #pragma unroll
        for (int b = 0; b < 4; b++)
            #pragma unroll
            for (int c = 0; c < 4; c++) acc[a][b][c] = 0.f;

    stage_tiles4(sm_u,         g_xh, g_xl, g_yh, g_yl, D_SZ, D_SZ, m0, n0, 0,  tid);
    stage_tiles4(sm_u + 32768, g_xh, g_xl, g_yh, g_yl, D_SZ, D_SZ, m0, n0, 32, tid);

    for (int c = 0; c < QK_CHUNKS; c++) {
        unsigned sb = sm_u + (unsigned)(c & 1) * 32768;
        if (c + 1 < QK_CHUNKS) { CP_WAIT_1(); } else { CP_WAIT_0(); }
        __syncthreads();
        compute_chunk3(sb, wm, wn, lane, acc);
        __syncthreads();
        if (c + 2 < QK_CHUNKS)
            stage_tiles4(sb, g_xh, g_xl, g_yh, g_yl, D_SZ, D_SZ, m0, n0,
                         (size_t)(c + 2) * 32, tid);
    }

    int mg = m0 + wm * 64, ng = n0 + wn * 32;
    #pragma unroll
    for (int mf = 0; mf < 4; mf++) {
        int r1 = mg + mf * 16 + (lane >> 2);
        int r2 = r1 + 8;
        float be1 = g_be[r1], be2 = g_be[r2];
        float mx1 = -1e30f, mx2 = -1e30f;
        #pragma unroll
        for (int nf = 0; nf < 4; nf++) {
            int col = ng + nf * 8 + (lane & 3) * 2;
            float d0 = g_dsn[col], d1 = g_dsn[col + 1];
            float2 o1 = make_float2(fmaf(-be1, d0, acc[mf][nf][0]),
                                    fmaf(-be1, d1, acc[mf][nf][1]));
            float2 o2 = make_float2(fmaf(-be2, d0, acc[mf][nf][2]),
                                    fmaf(-be2, d1, acc[mf][nf][3]));
            *(float2*)&g_logit[(size_t)r1 * NPAD + col] = o1;
            *(float2*)&g_logit[(size_t)r2 * NPAD + col] = o2;
            if (col < N_SZ) {            // mask pad keys out of the max
                mx1 = fmaxf(mx1, fmaxf(o1.x, o1.y));
                mx2 = fmaxf(mx2, fmaxf(o2.x, o2.y));
            }
        }
        mx1 = fmaxf(mx1, __shfl_xor_sync(0xffffffffu, mx1, 1));
        mx1 = fmaxf(mx1, __shfl_xor_sync(0xffffffffu, mx1, 2));
        mx2 = fmaxf(mx2, __shfl_xor_sync(0xffffffffu, mx2, 1));
        mx2 = fmaxf(mx2, __shfl_xor_sync(0xffffffffu, mx2, 2));
        if ((lane & 3) == 0) {
            smax[wn][wm * 64 + mf * 16 + (lane >> 2)]     = mx1;
            smax[wn][wm * 64 + mf * 16 + (lane >> 2) + 8] = mx2;
        }
    }
    __syncthreads();
    if (tid < 128) {
        float m = fmaxf(fmaxf(smax[0][tid], smax[1][tid]),
                        fmaxf(smax[2][tid], smax[3][tid]));
        g_pm[(size_t)(m0 + tid) * NTILE + blockIdx.y] = m;
    }
}

// ---------------------------------------------------------------------------
// K2: row max (from per-tile partials) + P = exp(lg - m) -> fp16; L = sum(P)
// ---------------------------------------------------------------------------
__global__ void pexp_kernel()
{
    int row = blockIdx.x, tid = threadIdx.x;
    __shared__ float red[8];
    __shared__ float s_m;

    // 1) row max over 782 per-tile partials
    {
        const float* rp = g_pm + (size_t)row * NTILE;
        float m = -1e30f;
        for (int c = tid; c < NTILE; c += 256) m = fmaxf(m, rp[c]);
        #pragma unroll
        for (int off = 16; off > 0; off >>= 1)
            m = fmaxf(m, __shfl_xor_sync(0xffffffffu, m, off));
        if ((tid & 31) == 0) red[tid >> 5] = m;
        __syncthreads();
        if (tid == 0) {
            float mm = red[0];
            #pragma unroll
            for (int w = 1; w < 8; w++) mm = fmaxf(mm, red[w]);
            s_m = mm;
        }
        __syncthreads();
    }
    float mr = s_m;

    // 2) exponentiate + fp16 store + row sum
    const float4* rp = (const float4*)(g_logit + (size_t)row * NPAD);
    __half2* ph2 = (__half2*)(g_ph + (size_t)row * NPAD);
    float l = 0.f;
    for (int c = tid; c < N_SZ / 4; c += 256) {
        float4 v = rp[c];
        v.x = __expf(v.x - mr); v.y = __expf(v.y - mr);
        v.z = __expf(v.z - mr); v.w = __expf(v.w - mr);
        l += (v.x + v.y) + (v.z + v.w);
        ph2[c * 2]     = __halves2half2(__float2half_rn(v.x), __float2half_rn(v.y));
        ph2[c * 2 + 1] = __halves2half2(__float2half_rn(v.z), __float2half_rn(v.w));
    }
    #pragma unroll
    for (int off = 16; off > 0; off >>= 1)
        l += __shfl_xor_sync(0xffffffffu, l, off);
    __syncthreads();
    if ((tid & 31) == 0) red[tid >> 5] = l;
    __syncthreads();
    if (tid == 0) {
        float s = red[0];
        #pragma unroll
        for (int w = 1; w < 8; w++) s += red[w];
        g_L[row] = s;
    }
}

// ---------------------------------------------------------------------------
// K3: PV GEMM (fp16 1-pass HMMA), split-K over 4 splits, k64 chunks.
// C[q][d] = sum_k P[q][k] * yT[d][k] -> g_pv[split]
// ---------------------------------------------------------------------------
__global__ __launch_bounds__(256) void pv_mma_kernel()
{
    extern __shared__ char smem_raw[];
    const unsigned sm_u = (unsigned)__cvta_generic_to_shared(smem_raw);
    const int tid = threadIdx.x, lane = tid & 31, warp = tid >> 5;
    const int wm = warp >> 2, wn = warp & 3;
    const int m0 = (blockIdx.x >> 2) * 128;   // queries
    const int n0 = (blockIdx.x & 3) * 128;    // d dims
    const int split = blockIdx.y;
    const size_t kh0 = (size_t)split * PV_KSPL;

    float acc[4][4][4];
    #pragma unroll
    for (int a = 0; a < 4; a++)
        #pragma unroll
        for (int b = 0; b < 4; b++)
            #pragma unroll
            for (int c = 0; c < 4; c++) acc[a][b][c] = 0.f;

    stage_pv(sm_u,         g_ph, g_yth, NPAD, NPAD, m0, n0, kh0,      tid);
    stage_pv(sm_u + 32768, g_ph, g_yth, NPAD, NPAD, m0, n0, kh0 + 64, tid);

    for (int c = 0; c < PV_CHUNKS; c++) {
        unsigned sb = sm_u + (unsigned)(c & 1) * 32768;
        if (c + 1 < PV_CHUNKS) { CP_WAIT_1(); } else { CP_WAIT_0(); }
        __syncthreads();
        compute_pv(sb, wm, wn, lane, acc);
        __syncthreads();
        if (c + 2 < PV_CHUNKS)
            stage_pv(sb, g_ph, g_yth, NPAD, NPAD, m0, n0,
                     kh0 + (size_t)(c + 2) * 64, tid);
    }

    int mg = m0 + wm * 64, ng = n0 + wn * 32;
    #pragma unroll
    for (int mf = 0; mf < 4; mf++) {
        int r1 = mg + mf * 16 + (lane >> 2);
        int r2 = r1 + 8;
        #pragma unroll
        for (int nf = 0; nf < 4; nf++) {
            int col = ng + nf * 8 + (lane & 3) * 2;
            size_t b1 = ((size_t)split * B_SZ + r1) * D_SZ + col;
            size_t b2 = ((size_t)split * B_SZ + r2) * D_SZ + col;
            *(float2*)&g_pv[b1] = make_float2(acc[mf][nf][0], acc[mf][nf][1]);
            *(float2*)&g_pv[b2] = make_float2(acc[mf][nf][2], acc[mf][nf][3]);
        }
    }
}

// ---------------------------------------------------------------------------
// K4: combine splits + final affine. v = c1*x + (c2/L) * sum_s pv[s]
// ---------------------------------------------------------------------------
__global__ void combine_kernel(const float* __restrict__ x,
                               float* __restrict__ out)
{
    int row = blockIdx.x, tid = threadIdx.x;   // 128 threads, one float4 each
    const float4* pv4 = (const float4*)g_pv;
    float4 s = make_float4(0.f, 0.f, 0.f, 0.f);
    #pragma unroll
    for (int sp = 0; sp < PV_SPLITS; sp++) {
        float4 v = pv4[((size_t)sp * B_SZ + row) * D4 + tid];
        s.x += v.x; s.y += v.y; s.z += v.z; s.w += v.w;
    }
    float c1 = g_c1[row];
    float c2 = g_c2[row] / g_L[row];
    float4 xv = ((const float4*)x)[(size_t)row * D4 + tid];
    float4 o;
    o.x = fmaf(c1, xv.x, c2 * s.x);
    o.y = fmaf(c1, xv.y, c2 * s.y);
    o.z = fmaf(c1, xv.z, c2 * s.z);
    o.w = fmaf(c1, xv.w, c2 * s.w);
    ((float4*)out)[(size_t)row * D4 + tid] = o;
}

// ---------------------------------------------------------------------------
extern "C" void kernel_launch(void* const* d_in, const int* in_sizes, int n_in,
                              void* d_out, int out_size)
{
    const float* x = (const float*)d_in[0];   // x_t (1024,512)
    const float* t = (const float*)d_in[1];   // t (1024,)
    const float* y = (const float*)d_in[2];   // dataset (100000,512)
    float* out = (float*)d_out;

    static int attr_set = 0;
    if (!attr_set) {
        cudaFuncSetAttribute(qk_mma_kernel,
            cudaFuncAttributeMaxDynamicSharedMemorySize, SMEM_MMA);
        cudaFuncSetAttribute(pv_mma_kernel,
            cudaFuncAttributeMaxDynamicSharedMemorySize, SMEM_MMA);
        attr_set = 1;
    }

    prep_kernel<<<12565, 256>>>(x, t, y);
    ysplit_kernel<<<dim3(3125, 4), 256>>>(y);
    qk_mma_kernel<<<dim3(8, NTILE), 256, SMEM_MMA>>>();
    pexp_kernel<<<B_SZ, 256>>>();
    pv_mma_kernel<<<dim3(32, PV_SPLITS), 256, SMEM_MMA>>>();
    combine_kernel<<<B_SZ, 128>>>(x, out);
}

// round 17
// speedup vs baseline: 6.6075x; 1.2678x over previous
#include <cuda_runtime.h>
#include <cuda_fp16.h>
#include <math.h>
#include <stdint.h>

// Problem shapes (fixed)
#define B_SZ 1024
#define N_SZ 100000
#define D_SZ 512
#define NPAD 100096              // 782*128
#define NTILE 782
#define NGRP  (NPAD/32)          // 3128 per-row 32-col groups
#define D4   (D_SZ/4)

#define QK_CHUNKS 16             // K=512 / 32
#define PV_SPLITS 4
#define PV_KSPL   (NPAD/PV_SPLITS)     // 25024
#define PV_CHUNKS (PV_KSPL/64)         // 391 (k64 chunks)

#define SMEM_MMA 98304           // 3 stages * 32KB

// ---------------- scratch (zero-initialized static device globals) ---------
__device__ __half g_xh[B_SZ * D_SZ], g_xl[B_SZ * D_SZ];     // al-scaled x split
__device__ __half g_yh[(size_t)NPAD * D_SZ], g_yl[(size_t)NPAD * D_SZ];   // y [n][d]
__device__ __half g_yth[(size_t)D_SZ * NPAD];                // y^T hi [d][n]
__device__ __half g_ph[(size_t)B_SZ * NPAD];                 // P fp16 (pad 0)
__device__ __half g_lh[(size_t)B_SZ * NPAD];                 // logit fp16, grp-max-rel
__device__ float g_be[B_SZ], g_c1[B_SZ], g_c2[B_SZ];
__device__ float g_dsn[NPAD];                                // pad stays 0
__device__ float g_pm[(size_t)B_SZ * NGRP];                  // per-group row maxes
__device__ float g_L[B_SZ];
__device__ float g_pv[(size_t)PV_SPLITS * B_SZ * D_SZ];

// ---------------- helpers ---------------------------------------------------
__device__ __forceinline__ void cp16(unsigned dst, const void* src) {
    asm volatile("cp.async.cg.shared.global [%0], [%1], 16;" :: "r"(dst), "l"(src));
}
#define CP_COMMIT() asm volatile("cp.async.commit_group;")
#define CP_WAIT_1() asm volatile("cp.async.wait_group 1;" ::: "memory")
#define CP_WAIT_0() asm volatile("cp.async.wait_group 0;" ::: "memory")

#define LDSM_X4(r, a) \
    asm volatile("ldmatrix.sync.aligned.m8n8.x4.shared.b16 {%0,%1,%2,%3},[%4];" \
        : "=r"((r)[0]), "=r"((r)[1]), "=r"((r)[2]), "=r"((r)[3]) : "r"(a))
#define MMA16816(c, A, b0, b1) \
    asm volatile("mma.sync.aligned.m16n8k16.row.col.f32.f16.f16.f32 " \
        "{%0,%1,%2,%3},{%4,%5,%6,%7},{%8,%9},{%0,%1,%2,%3};" \
        : "+f"((c)[0]), "+f"((c)[1]), "+f"((c)[2]), "+f"((c)[3]) \
        : "r"((A)[0]), "r"((A)[1]), "r"((A)[2]), "r"((A)[3]), "r"(b0), "r"(b1))

// ---- QK staging (k32 rows of 64B, swizzle c^((row>>1)&3)) ------------------
__device__ __forceinline__ void stage_tiles4(unsigned sb,
    const __half* __restrict__ Ah, const __half* __restrict__ Al,
    const __half* __restrict__ Bh, const __half* __restrict__ Bl,
    int ar0, int br0, size_t kh, int tid)
{
    #pragma unroll
    for (int q = 0; q < 2; q++) {
        int i = tid + 256 * q;
        int row = i >> 2, c = i & 3;
        unsigned sw = (unsigned)(row * 64 + ((c ^ ((row >> 1) & 3)) << 4));
        size_t ka = kh + c * 8;
        size_t ra = (size_t)(ar0 + row) * D_SZ + ka;
        size_t rb = (size_t)(br0 + row) * D_SZ + ka;
        cp16(sb +         sw, Ah + ra);
        cp16(sb +  8192 + sw, Al + ra);
        cp16(sb + 16384 + sw, Bh + rb);
        cp16(sb + 24576 + sw, Bl + rb);
    }
    CP_COMMIT();
}

// QK chunk: 3 passes (ah*bh, al*bh, ah*bl); warp tile 64x32
__device__ __forceinline__ void compute_chunk3(unsigned sb, int wm, int wn,
                                               int lane, float (&acc)[4][4][4])
{
    #pragma unroll
    for (int ks = 0; ks < 2; ks++) {
        uint32_t ah[4][4], al[4][4], bh[2][4], bl[2][4];
        #pragma unroll
        for (int mf = 0; mf < 4; mf++) {
            int row = wm * 64 + mf * 16 + (lane & 15);
            int c16 = ks * 2 + (lane >> 4);
            unsigned off = (unsigned)(row * 64 + ((c16 ^ ((row >> 1) & 3)) << 4));
            LDSM_X4(ah[mf], sb + off);
            LDSM_X4(al[mf], sb + 8192 + off);
        }
        #pragma unroll
        for (int nf2 = 0; nf2 < 2; nf2++) {
            int row = wn * 32 + nf2 * 16 + (lane & 7) + ((lane >> 4) << 3);
            int c16 = ks * 2 + ((lane >> 3) & 1);
            unsigned off = (unsigned)(row * 64 + ((c16 ^ ((row >> 1) & 3)) << 4));
            LDSM_X4(bh[nf2], sb + 16384 + off);
            LDSM_X4(bl[nf2], sb + 24576 + off);
        }
        #pragma unroll
        for (int mf = 0; mf < 4; mf++)
            #pragma unroll
            for (int nf = 0; nf < 4; nf++)
                MMA16816(acc[mf][nf], ah[mf],
                         bh[nf >> 1][(nf & 1) * 2], bh[nf >> 1][(nf & 1) * 2 + 1]);
        #pragma unroll
        for (int mf = 0; mf < 4; mf++)
            #pragma unroll
            for (int nf = 0; nf < 4; nf++)
                MMA16816(acc[mf][nf], al[mf],
                         bh[nf >> 1][(nf & 1) * 2], bh[nf >> 1][(nf & 1) * 2 + 1]);
        #pragma unroll
        for (int mf = 0; mf < 4; mf++)
            #pragma unroll
            for (int nf = 0; nf < 4; nf++)
                MMA16816(acc[mf][nf], ah[mf],
                         bl[nf >> 1][(nf & 1) * 2], bl[nf >> 1][(nf & 1) * 2 + 1]);
    }
}

// ---- PV staging (k64 rows of 128B, swizzle c^(row&7)) ----------------------
__device__ __forceinline__ void stage_pv(unsigned sb,
    const __half* __restrict__ Ah, const __half* __restrict__ Bh,
    int ar0, int br0, size_t kh, int tid)
{
    #pragma unroll
    for (int q = 0; q < 4; q++) {
        int i = tid + 256 * q;           // 1024 = 128 rows * 8 c16
        int row = i >> 3, c = i & 7;
        unsigned sw = (unsigned)(row * 128 + ((c ^ (row & 7)) << 4));
        size_t ka = kh + c * 8;
        cp16(sb +         sw, Ah + (size_t)(ar0 + row) * NPAD + ka);
        cp16(sb + 16384 + sw, Bh + (size_t)(br0 + row) * NPAD + ka);
    }
    CP_COMMIT();
}

// PV chunk (k64, 1 pass): warp tile 64x32
__device__ __forceinline__ void compute_pv(unsigned sb, int wm, int wn,
                                           int lane, float (&acc)[4][4][4])
{
    #pragma unroll
    for (int ks = 0; ks < 4; ks++) {
        uint32_t ah[4][4], bh[2][4];
        #pragma unroll
        for (int mf = 0; mf < 4; mf++) {
            int row = wm * 64 + mf * 16 + (lane & 15);
            int c16 = ks * 2 + (lane >> 4);
            unsigned off = (unsigned)(row * 128 + ((c16 ^ (row & 7)) << 4));
            LDSM_X4(ah[mf], sb + off);
        }
        #pragma unroll
        for (int nf2 = 0; nf2 < 2; nf2++) {
            int row = wn * 32 + nf2 * 16 + (lane & 7) + ((lane >> 4) << 3);
            int c16 = ks * 2 + ((lane >> 3) & 1);
            unsigned off = (unsigned)(row * 128 + ((c16 ^ (row & 7)) << 4));
            LDSM_X4(bh[nf2], sb + 16384 + off);
        }
        #pragma unroll
        for (int mf = 0; mf < 4; mf++)
            #pragma unroll
            for (int nf = 0; nf < 4; nf++)
                MMA16816(acc[mf][nf], ah[mf],
                         bh[nf >> 1][(nf & 1) * 2], bh[nf >> 1][(nf & 1) * 2 + 1]);
    }
}

// ---------------------------------------------------------------------------
// K0 prep: dsn (blocks 0..12499); coeffs (12500); x' = (a/b^2)x fp16 split
// ---------------------------------------------------------------------------
__global__ void prep_kernel(const float* __restrict__ x,
                            const float* __restrict__ t,
                            const float* __restrict__ y)
{
    int bid = blockIdx.x, tid = threadIdx.x;
    if (bid < 12500) {
        int warp = tid >> 5, lane = tid & 31;
        int n = bid * 8 + warp;
        const float4* y4 = (const float4*)y;
        float s = 0.f;
        #pragma unroll
        for (int k = 0; k < 4; k++) {
            float4 v = y4[(size_t)n * D4 + lane + 32 * k];
            s = fmaf(v.x, v.x, fmaf(v.y, v.y, fmaf(v.z, v.z, fmaf(v.w, v.w, s))));
        }
        #pragma unroll
        for (int off = 16; off > 0; off >>= 1)
            s += __shfl_xor_sync(0xffffffffu, s, off);
        if (lane == 0) g_dsn[n] = s;
    } else if (bid == 12500) {
        #pragma unroll
        for (int q = 0; q < 4; q++) {
            int r = tid + 256 * q;
            float a = t[r], b = 1.f - a;
            g_be[r] = a * a / (2.f * b * b);
            g_c1[r] = -1.f / b;
            g_c2[r] = 1.f + a / b;
        }
    } else {
        int base = (bid - 12501) * 2048;
        const float4* x4 = (const float4*)x;
        #pragma unroll
        for (int q = 0; q < 8; q++) {
            int i = base + tid + 256 * q;
            int row = i >> 7;
            float tv = t[row], b = 1.f - tv;
            float al = tv / (b * b);
            float4 v = x4[i];
            v.x *= al; v.y *= al; v.z *= al; v.w *= al;
            __half hx = __float2half_rn(v.x), hy = __float2half_rn(v.y);
            __half hz = __float2half_rn(v.z), hw = __float2half_rn(v.w);
            __half lx = __float2half_rn(v.x - __half2float(hx));
            __half ly = __float2half_rn(v.y - __half2float(hy));
            __half lz = __float2half_rn(v.z - __half2float(hz));
            __half lw = __float2half_rn(v.w - __half2float(hw));
            size_t a2 = (size_t)i * 2;   // half2 index
            ((__half2*)g_xh)[a2]     = __halves2half2(hx, hy);
            ((__half2*)g_xh)[a2 + 1] = __halves2half2(hz, hw);
            ((__half2*)g_xl)[a2]     = __halves2half2(lx, ly);
            ((__half2*)g_xl)[a2 + 1] = __halves2half2(lz, lw);
        }
    }
}

// ---------------------------------------------------------------------------
// K0b: y fp16 split [n][d] (hi+lo) and transposed hi [d][n] (pad stays 0)
// ---------------------------------------------------------------------------
__global__ void ysplit_kernel(const float* __restrict__ y)
{
    __shared__ float tile[32][129];
    int tid = threadIdx.x;
    int n0 = blockIdx.x * 32;
    int d0 = blockIdx.y * 128;

    #pragma unroll
    for (int q = 0; q < 8; q++) {
        int i = tid + 256 * q;           // 2048: (n, d-pair)
        int r = i >> 6, c2 = i & 63;
        float v0 = y[(size_t)(n0 + r) * D_SZ + d0 + 2 * c2];
        float v1 = y[(size_t)(n0 + r) * D_SZ + d0 + 2 * c2 + 1];
        tile[r][2 * c2] = v0; tile[r][2 * c2 + 1] = v1;
        __half h0 = __float2half_rn(v0), h1 = __float2half_rn(v1);
        __half l0 = __float2half_rn(v0 - __half2float(h0));
        __half l1 = __float2half_rn(v1 - __half2float(h1));
        size_t a = (size_t)(n0 + r) * D_SZ + d0 + 2 * c2;
        ((__half2*)g_yh)[a >> 1] = __halves2half2(h0, h1);
        ((__half2*)g_yl)[a >> 1] = __halves2half2(l0, l1);
    }
    __syncthreads();
    #pragma unroll
    for (int q = 0; q < 8; q++) {
        int i = tid + 256 * q;           // 2048: (d, n-pair)
        int d = i >> 4, np = i & 15;
        float v0 = tile[2 * np][d], v1 = tile[2 * np + 1][d];
        __half h0 = __float2half_rn(v0), h1 = __float2half_rn(v1);
        size_t a = (size_t)(d0 + d) * NPAD + n0 + 2 * np;
        ((__half2*)g_yth)[a >> 1] = __halves2half2(h0, h1);
    }
}

// ---------------------------------------------------------------------------
// K1: QK GEMM (fp16x3 HMMA), 3-stage pipeline, 1 sync/chunk.
// Epilogue: per-32-col-group row max -> g_pm; store lg - m_grp as fp16.
// ---------------------------------------------------------------------------
__global__ __launch_bounds__(256) void qk_mma_kernel()
{
    extern __shared__ char smem_raw[];
    const unsigned sm_u = (unsigned)__cvta_generic_to_shared(smem_raw);
    const int tid = threadIdx.x, lane = tid & 31, warp = tid >> 5;
    const int wm = warp >> 2, wn = warp & 3;
    const int m0 = blockIdx.x * 128;     // queries
    const int n0 = blockIdx.y * 128;     // keys

    float acc[4][4][4];
    #pragma unroll
    for (int a = 0; a < 4; a++)
        #pragma unroll
        for (int b = 0; b < 4; b++)
            #pragma unroll
            for (int c = 0; c < 4; c++) acc[a][b][c] = 0.f;

    stage_tiles4(sm_u,         g_xh, g_xl, g_yh, g_yl, m0, n0, 0,  tid);
    stage_tiles4(sm_u + 32768, g_xh, g_xl, g_yh, g_yl, m0, n0, 32, tid);

    int bc = 0, bs = 2;
    for (int c = 0; c < QK_CHUNKS; c++) {
        if (c + 1 < QK_CHUNKS) { CP_WAIT_1(); } else { CP_WAIT_0(); }
        __syncthreads();
        compute_chunk3(sm_u + (unsigned)bc * 32768, wm, wn, lane, acc);
        if (c + 2 < QK_CHUNKS)
            stage_tiles4(sm_u + (unsigned)bs * 32768, g_xh, g_xl, g_yh, g_yl,
                         m0, n0, (size_t)(c + 2) * 32, tid);
        bc = (bc == 2) ? 0 : bc + 1;
        bs = (bs == 2) ? 0 : bs + 1;
    }

    // epilogue: lg = C - be*dsn ; per-group max ; store fp16 (lg - max)
    int mg = m0 + wm * 64, ng = n0 + wn * 32;
    int grp = (n0 >> 5) + wn;
    #pragma unroll
    for (int mf = 0; mf < 4; mf++) {
        int r1 = mg + mf * 16 + (lane >> 2);
        int r2 = r1 + 8;
        float be1 = g_be[r1], be2 = g_be[r2];
        float2 o1[4], o2[4];
        float mx1 = -1e30f, mx2 = -1e30f;
        #pragma unroll
        for (int nf = 0; nf < 4; nf++) {
            int col = ng + nf * 8 + (lane & 3) * 2;
            float d0 = g_dsn[col], d1 = g_dsn[col + 1];
            o1[nf] = make_float2(fmaf(-be1, d0, acc[mf][nf][0]),
                                 fmaf(-be1, d1, acc[mf][nf][1]));
            o2[nf] = make_float2(fmaf(-be2, d0, acc[mf][nf][2]),
                                 fmaf(-be2, d1, acc[mf][nf][3]));
            if (col < N_SZ) {            // groups are all-valid or all-invalid
                mx1 = fmaxf(mx1, fmaxf(o1[nf].x, o1[nf].y));
                mx2 = fmaxf(mx2, fmaxf(o2[nf].x, o2[nf].y));
            }
        }
        mx1 = fmaxf(mx1, __shfl_xor_sync(0xffffffffu, mx1, 1));
        mx1 = fmaxf(mx1, __shfl_xor_sync(0xffffffffu, mx1, 2));
        mx2 = fmaxf(mx2, __shfl_xor_sync(0xffffffffu, mx2, 1));
        mx2 = fmaxf(mx2, __shfl_xor_sync(0xffffffffu, mx2, 2));
        #pragma unroll
        for (int nf = 0; nf < 4; nf++) {
            int col = ng + nf * 8 + (lane & 3) * 2;
            *(__half2*)&g_lh[(size_t)r1 * NPAD + col] =
                __floats2half2_rn(o1[nf].x - mx1, o1[nf].y - mx1);
            *(__half2*)&g_lh[(size_t)r2 * NPAD + col] =
                __floats2half2_rn(o2[nf].x - mx2, o2[nf].y - mx2);
        }
        if ((lane & 3) == 0) {
            g_pm[(size_t)r1 * NGRP + grp] = mx1;
            g_pm[(size_t)r2 * NGRP + grp] = mx2;
        }
    }
}

// ---------------------------------------------------------------------------
// K2: row max over group partials + P = exp(lg_h + m_grp - m) -> fp16; L
// ---------------------------------------------------------------------------
__global__ void pexp_kernel()
{
    int row = blockIdx.x, tid = threadIdx.x;
    __shared__ float red[8];
    __shared__ float s_m;
    const float* pm = g_pm + (size_t)row * NGRP;

    // 1) row max over 3128 per-group partials
    {
        float m = -1e30f;
        for (int c = tid; c < NGRP; c += 256) m = fmaxf(m, pm[c]);
        #pragma unroll
        for (int off = 16; off > 0; off >>= 1)
            m = fmaxf(m, __shfl_xor_sync(0xffffffffu, m, off));
        if ((tid & 31) == 0) red[tid >> 5] = m;
        __syncthreads();
        if (tid == 0) {
            float mm = red[0];
            #pragma unroll
            for (int w = 1; w < 8; w++) mm = fmaxf(mm, red[w]);
            s_m = mm;
        }
        __syncthreads();
    }
    float mr = s_m;

    // 2) P = exp(lg_stored + (m_grp - m)); fp16 store; row sum
    const uint4* lrow = (const uint4*)(g_lh + (size_t)row * NPAD);
    __half2* ph2 = (__half2*)(g_ph + (size_t)row * NPAD);
    float l = 0.f;
    for (int i = tid; i < N_SZ / 8; i += 256) {     // 8 halves per iter
        float add = pm[i >> 2] - mr;
        uint4 u = lrow[i];
        float2 f0 = __half22float2(*(__half2*)&u.x);
        float2 f1 = __half22float2(*(__half2*)&u.y);
        float2 f2 = __half22float2(*(__half2*)&u.z);
        float2 f3 = __half22float2(*(__half2*)&u.w);
        float e0 = __expf(f0.x + add), e1 = __expf(f0.y + add);
        float e2 = __expf(f1.x + add), e3 = __expf(f1.y + add);
        float e4 = __expf(f2.x + add), e5 = __expf(f2.y + add);
        float e6 = __expf(f3.x + add), e7 = __expf(f3.y + add);
        l += ((e0 + e1) + (e2 + e3)) + ((e4 + e5) + (e6 + e7));
        ph2[i * 4 + 0] = __floats2half2_rn(e0, e1);
        ph2[i * 4 + 1] = __floats2half2_rn(e2, e3);
        ph2[i * 4 + 2] = __floats2half2_rn(e4, e5);
        ph2[i * 4 + 3] = __floats2half2_rn(e6, e7);
    }
    #pragma unroll
    for (int off = 16; off > 0; off >>= 1)
        l += __shfl_xor_sync(0xffffffffu, l, off);
    __syncthreads();
    if ((tid & 31) == 0) red[tid >> 5] = l;
    __syncthreads();
    if (tid == 0) {
        float s = red[0];
        #pragma unroll
        for (int w = 1; w < 8; w++) s += red[w];
        g_L[row] = s;
    }
}

// ---------------------------------------------------------------------------
// K3: PV GEMM (fp16 1-pass HMMA), split-K 4, k64 chunks, 3-stage pipeline.
// ---------------------------------------------------------------------------
__global__ __launch_bounds__(256) void pv_mma_kernel()
{
    extern __shared__ char smem_raw[];
    const unsigned sm_u = (unsigned)__cvta_generic_to_shared(smem_raw);
    const int tid = threadIdx.x, lane = tid & 31, warp = tid >> 5;
    const int wm = warp >> 2, wn = warp & 3;
    const int m0 = (blockIdx.x >> 2) * 128;   // queries
    const int n0 = (blockIdx.x & 3) * 128;    // d dims
    const int split = blockIdx.y;
    const size_t kh0 = (size_t)split * PV_KSPL;

    float acc[4][4][4];
    #pragma unroll
    for (int a = 0; a < 4; a++)
        #pragma unroll
        for (int b = 0; b < 4; b++)
            #pragma unroll
            for (int c = 0; c < 4; c++) acc[a][b][c] = 0.f;

    stage_pv(sm_u,         g_ph, g_yth, m0, n0, kh0,      tid);
    stage_pv(sm_u + 32768, g_ph, g_yth, m0, n0, kh0 + 64, tid);

    int bc = 0, bs = 2;
    for (int c = 0; c < PV_CHUNKS; c++) {
        if (c + 1 < PV_CHUNKS) { CP_WAIT_1(); } else { CP_WAIT_0(); }
        __syncthreads();
        compute_pv(sm_u + (unsigned)bc * 32768, wm, wn, lane, acc);
        if (c + 2 < PV_CHUNKS)
            stage_pv(sm_u + (unsigned)bs * 32768, g_ph, g_yth, m0, n0,
                     kh0 + (size_t)(c + 2) * 64, tid);
        bc = (bc == 2) ? 0 : bc + 1;
        bs = (bs == 2) ? 0 : bs + 1;
    }

    int mg = m0 + wm * 64, ng = n0 + wn * 32;
    #pragma unroll
    for (int mf = 0; mf < 4; mf++) {
        int r1 = mg + mf * 16 + (lane >> 2);
        int r2 = r1 + 8;
        #pragma unroll
        for (int nf = 0; nf < 4; nf++) {
            int col = ng + nf * 8 + (lane & 3) * 2;
            size_t b1 = ((size_t)split * B_SZ + r1) * D_SZ + col;
            size_t b2 = ((size_t)split * B_SZ + r2) * D_SZ + col;
            *(float2*)&g_pv[b1] = make_float2(acc[mf][nf][0], acc[mf][nf][1]);
            *(float2*)&g_pv[b2] = make_float2(acc[mf][nf][2], acc[mf][nf][3]);
        }
    }
}

// ---------------------------------------------------------------------------
// K4: combine splits + final affine. v = c1*x + (c2/L) * sum_s pv[s]
// ---------------------------------------------------------------------------
__global__ void combine_kernel(const float* __restrict__ x,
                               float* __restrict__ out)
{
    int row = blockIdx.x, tid = threadIdx.x;   // 128 threads, one float4 each
    const float4* pv4 = (const float4*)g_pv;
    float4 s = make_float4(0.f, 0.f, 0.f, 0.f);
    #pragma unroll
    for (int sp = 0; sp < PV_SPLITS; sp++) {
        float4 v = pv4[((size_t)sp * B_SZ + row) * D4 + tid];
        s.x += v.x; s.y += v.y; s.z += v.z; s.w += v.w;
    }
    float c1 = g_c1[row];
    float c2 = g_c2[row] / g_L[row];
    float4 xv = ((const float4*)x)[(size_t)row * D4 + tid];
    float4 o;
    o.x = fmaf(c1, xv.x, c2 * s.x);
    o.y = fmaf(c1, xv.y, c2 * s.y);
    o.z = fmaf(c1, xv.z, c2 * s.z);
    o.w = fmaf(c1, xv.w, c2 * s.w);
    ((float4*)out)[(size_t)row * D4 + tid] = o;
}

// ---------------------------------------------------------------------------
extern "C" void kernel_launch(void* const* d_in, const int* in_sizes, int n_in,
                              void* d_out, int out_size)
{
    const float* x = (const float*)d_in[0];   // x_t (1024,512)
    const float* t = (const float*)d_in[1];   // t (1024,)
    const float* y = (const float*)d_in[2];   // dataset (100000,512)
    float* out = (float*)d_out;

    static int attr_set = 0;
    if (!attr_set) {
        cudaFuncSetAttribute(qk_mma_kernel,
            cudaFuncAttributeMaxDynamicSharedMemorySize, SMEM_MMA);
        cudaFuncSetAttribute(pv_mma_kernel,
            cudaFuncAttributeMaxDynamicSharedMemorySize, SMEM_MMA);
        attr_set = 1;
    }

    prep_kernel<<<12565, 256>>>(x, t, y);
    ysplit_kernel<<<dim3(3125, 4), 256>>>(y);
    qk_mma_kernel<<<dim3(8, NTILE), 256, SMEM_MMA>>>();
    pexp_kernel<<<B_SZ, 256>>>();
    pv_mma_kernel<<<dim3(32, PV_SPLITS), 256, SMEM_MMA>>>();
    combine_kernel<<<B_SZ, 128>>>(x, out);
}